// round 1
// baseline (speedup 1.0000x reference)
#include <cuda_runtime.h>
#include <cstdint>
#include <math.h>

#define Bq 8
#define Ntok 9237
#define Cc 512
#define Tt 21
#define Hh 8
#define Dd 64
#define HIDN 2048
#define M_ROWS (Bq*Ntok)          // 73896
#define EPSV 1e-5f
#define SCALEV 0.125f
#define NSEG 37                    // ceil(9237/256)

// ---------------- static scratch (no allocations allowed) ----------------
__device__ __align__(16) float g_mean[M_ROWS];
__device__ __align__(16) float g_rstd[M_ROWS];
__device__ __align__(16) float g_Wcat[512*1536];
__device__ __align__(16) float g_biasc[1536];
__device__ __align__(16) float g_K0[(size_t)Bq*Hh*Ntok*Dd];
__device__ __align__(16) float g_V0[(size_t)Bq*Hh*Ntok*Dd];
__device__ __align__(16) float g_K1[(size_t)Bq*Hh*Ntok*Dd];
__device__ __align__(16) float g_q0[Bq*Tt*Cc];
__device__ __align__(16) float g_q1[Bq*Tt*Cc];
__device__ __align__(16) float g_Pacc[(size_t)Bq*Hh*NSEG*Tt*Dd];
__device__ __align__(16) float g_Psum[Bq*Hh*NSEG*Tt];
__device__ __align__(16) float g_ce[Bq*Tt*Cc];
__device__ __align__(16) float g_Fmax[Bq*Hh*NSEG*Tt];
__device__ __align__(16) float g_Fsum[Bq*Hh*NSEG*Tt];
__device__ __align__(16) float g_Mrow[Bq*Hh*Tt];
__device__ __align__(16) float g_Tinv[Bq*Hh*Tt];

// ---------------- K1: prep fused weights + folded bias row ----------------
__global__ void k_prep(const float* __restrict__ kv0_w, const float* __restrict__ kv1_w,
                       const float* __restrict__ g1, const float* __restrict__ b1,
                       const float* __restrict__ g3, const float* __restrict__ b3) {
    int j = blockIdx.x * blockDim.x + threadIdx.x;
    if (j >= 1536) return;
    float cacc = 0.f;
    if (j < 1024) {
        for (int k = 0; k < 512; k++) {
            float w = kv0_w[(size_t)k*1024 + j];
            g_Wcat[(size_t)k*1536 + j] = g1[k]*w;
            cacc += b1[k]*w;
        }
    } else {
        int jj = j - 1024;
        for (int k = 0; k < 512; k++) {
            float w = kv1_w[(size_t)k*1024 + jj];
            g_Wcat[(size_t)k*1536 + j] = g3[k]*w;
            cacc += b3[k]*w;
        }
    }
    g_biasc[j] = cacc;
}

// ---------------- K2: per-row LN stats ----------------
__global__ void k_stats(const float* __restrict__ x) {
    int row = blockIdx.x * 8 + threadIdx.y;
    if (row >= M_ROWS) return;
    const float4* xr = (const float4*)(x + (size_t)row*512);
    float s = 0.f, sq = 0.f;
    for (int i = threadIdx.x; i < 128; i += 32) {
        float4 v = xr[i];
        s  += v.x + v.y + v.z + v.w;
        sq += v.x*v.x + v.y*v.y + v.z*v.z + v.w*v.w;
    }
    for (int o = 16; o; o >>= 1) {
        s  += __shfl_down_sync(0xffffffffu, s, o);
        sq += __shfl_down_sync(0xffffffffu, sq, o);
    }
    if (threadIdx.x == 0) {
        float m = s * (1.f/512.f);
        float var = sq * (1.f/512.f) - m*m;
        g_mean[row] = m;
        g_rstd[row] = rsqrtf(var + EPSV);
    }
}

// ---------------- K3: fused LN + dual-weight GEMM (z @ Wcat) ----------------
__global__ __launch_bounds__(256) void k_gemm(const float* __restrict__ x) {
    __shared__ float As[2][16][128];
    __shared__ float Bs[2][16][128];
    const int tid = threadIdx.x;
    const int cb = blockIdx.x;             // 0..11
    const int rb = blockIdx.y;             // 0..577
    const int rowBase = rb * 128;
    const int colBase = cb * 128;

    const int arow = tid >> 2;             // 0..63
    const int acol = (tid & 3) * 4;        // 0,4,8,12
    const int brow = tid >> 5;             // 0..7
    const int bcol = (tid & 31) * 4;
    const int tx = tid & 15, ty = tid >> 4;

    const int r0 = rowBase + arow;
    const int r1 = r0 + 64;
    const bool v0ok = (r0 < M_ROWS);
    const bool v1ok = (r1 < M_ROWS);
    const float m0 = v0ok ? g_mean[r0] : 0.f, s0 = v0ok ? g_rstd[r0] : 0.f;
    const float m1 = v1ok ? g_mean[r1] : 0.f, s1 = v1ok ? g_rstd[r1] : 0.f;

    float acc[8][8];
    #pragma unroll
    for (int i = 0; i < 8; i++)
        #pragma unroll
        for (int j = 0; j < 8; j++) acc[i][j] = 0.f;

    float4 nA0, nA1, nB0, nB1;
    auto gload = [&](int kt) {
        int kk = kt*16 + acol;
        nA0 = v0ok ? *(const float4*)(x + (size_t)r0*512 + kk) : make_float4(0,0,0,0);
        nA1 = v1ok ? *(const float4*)(x + (size_t)r1*512 + kk) : make_float4(0,0,0,0);
        nA0.x = (nA0.x-m0)*s0; nA0.y = (nA0.y-m0)*s0; nA0.z = (nA0.z-m0)*s0; nA0.w = (nA0.w-m0)*s0;
        nA1.x = (nA1.x-m1)*s1; nA1.y = (nA1.y-m1)*s1; nA1.z = (nA1.z-m1)*s1; nA1.w = (nA1.w-m1)*s1;
        int gk = kt*16 + brow;
        nB0 = *(const float4*)(g_Wcat + (size_t)gk*1536 + colBase + bcol);
        nB1 = *(const float4*)(g_Wcat + (size_t)(gk+8)*1536 + colBase + bcol);
    };
    auto sstore = [&](int buf) {
        As[buf][acol+0][arow]   = nA0.x; As[buf][acol+1][arow]   = nA0.y;
        As[buf][acol+2][arow]   = nA0.z; As[buf][acol+3][arow]   = nA0.w;
        As[buf][acol+0][arow+64]= nA1.x; As[buf][acol+1][arow+64]= nA1.y;
        As[buf][acol+2][arow+64]= nA1.z; As[buf][acol+3][arow+64]= nA1.w;
        *(float4*)&Bs[buf][brow  ][bcol] = nB0;
        *(float4*)&Bs[buf][brow+8][bcol] = nB1;
    };

    gload(0); sstore(0); __syncthreads();
    int buf = 0;
    const int steps = 32;
    for (int kt = 0; kt < steps; kt++) {
        if (kt + 1 < steps) gload(kt + 1);
        #pragma unroll
        for (int kk = 0; kk < 16; kk++) {
            float4 a0 = *(float4*)&As[buf][kk][ty*4];
            float4 a1 = *(float4*)&As[buf][kk][64 + ty*4];
            float4 b0 = *(float4*)&Bs[buf][kk][tx*4];
            float4 b1 = *(float4*)&Bs[buf][kk][64 + tx*4];
            float av[8] = {a0.x,a0.y,a0.z,a0.w,a1.x,a1.y,a1.z,a1.w};
            float bv[8] = {b0.x,b0.y,b0.z,b0.w,b1.x,b1.y,b1.z,b1.w};
            #pragma unroll
            for (int i = 0; i < 8; i++)
                #pragma unroll
                for (int j = 0; j < 8; j++)
                    acc[i][j] = fmaf(av[i], bv[j], acc[i][j]);
        }
        if (kt + 1 < steps) { sstore(buf ^ 1); __syncthreads(); buf ^= 1; }
    }

    // epilogue: scatter into K0 / V0 / K1 ([b,h,n,d])
    #pragma unroll
    for (int ig = 0; ig < 2; ig++) {
        #pragma unroll
        for (int ii = 0; ii < 4; ii++) {
            int r = rowBase + ig*64 + ty*4 + ii;
            if (r >= M_ROWS) continue;
            int bb = r / Ntok, nt = r % Ntok;
            #pragma unroll
            for (int jg = 0; jg < 2; jg++) {
                int jglob = colBase + jg*64 + tx*4;
                float4 v;
                v.x = acc[ig*4+ii][jg*4+0] + g_biasc[jglob+0];
                v.y = acc[ig*4+ii][jg*4+1] + g_biasc[jglob+1];
                v.z = acc[ig*4+ii][jg*4+2] + g_biasc[jglob+2];
                v.w = acc[ig*4+ii][jg*4+3] + g_biasc[jglob+3];
                int region = jglob >> 9;
                int jr = jglob & 511;
                int h = jr >> 6, d = jr & 63;
                float* dst = (region == 0) ? g_K0 : (region == 1) ? g_V0 : g_K1;
                *(float4*)&dst[(((size_t)bb*Hh + h)*Ntok + nt)*64 + d] = v;
            }
        }
    }
}

// ---------------- K4: q0mat = ln1(x[:, :T]) @ q0_w ----------------
__global__ __launch_bounds__(512) void k_q0(const float* __restrict__ x,
                                            const float* __restrict__ q0_w,
                                            const float* __restrict__ g1,
                                            const float* __restrict__ b1) {
    int r = blockIdx.x;          // 0..167
    int b = r / Tt, t = r % Tt;
    int row = b*Ntok + t;
    __shared__ float y[512];
    int tid = threadIdx.x;
    float m = g_mean[row], rs = g_rstd[row];
    y[tid] = (x[(size_t)row*512 + tid] - m)*rs*g1[tid] + b1[tid];
    __syncthreads();
    float acc = 0.f;
    for (int k = 0; k < 512; k++) acc = fmaf(y[k], q0_w[(size_t)k*512 + tid], acc);
    g_q0[(size_t)r*512 + tid] = acc;
}

// ---------------- K5: attn0 partial (flash-style, unnormalized) ----------------
__global__ __launch_bounds__(256) void k_attn0() {
    int bh = blockIdx.x, seg = blockIdx.y;
    int b = bh >> 3, h = bh & 7;
    __shared__ float qs[Tt][64];
    __shared__ float Ks[64][65];
    __shared__ float Vs[64][65];
    __shared__ float ps[Tt][64];
    int tid = threadIdx.x;
    for (int i = tid; i < Tt*64; i += 256) {
        int t = i >> 6, d = i & 63;
        int flat = h*(Tt*Dd) + t*Dd + d;      // non-standard CaiT reshape
        qs[t][d] = SCALEV * g_q0[(size_t)b*Tt*512 + flat];
    }
    __syncthreads();
    int base = tid >> 6, nl = tid & 63;
    float acc[6] = {0,0,0,0,0,0};
    float ssum = 0.f;
    const float* Kb = g_K0 + (size_t)bh*Ntok*64;
    const float* Vb = g_V0 + (size_t)bh*Ntok*64;
    int n0 = seg*256;
    for (int ch = 0; ch < 4; ch++) {
        int nc = n0 + ch*64;
        for (int i = tid*4; i < 4096; i += 1024) {
            int nn = i >> 6, dd = i & 63;
            int gn = nc + nn;
            float4 kv = (gn < Ntok) ? *(const float4*)(Kb + (size_t)gn*64 + dd) : make_float4(0,0,0,0);
            float4 vv = (gn < Ntok) ? *(const float4*)(Vb + (size_t)gn*64 + dd) : make_float4(0,0,0,0);
            Ks[nn][dd]=kv.x; Ks[nn][dd+1]=kv.y; Ks[nn][dd+2]=kv.z; Ks[nn][dd+3]=kv.w;
            Vs[nn][dd]=vv.x; Vs[nn][dd+1]=vv.y; Vs[nn][dd+2]=vv.z; Vs[nn][dd+3]=vv.w;
        }
        __syncthreads();
        bool valid = (nc + nl) < Ntok;
        for (int t = base; t < Tt; t += 4) {
            float l = 0.f;
            #pragma unroll
            for (int d = 0; d < 64; d++) l = fmaf(qs[t][d], Ks[nl][d], l);
            ps[t][nl] = valid ? __expf(l) : 0.f;
        }
        __syncthreads();
        if (tid < Tt) {
            float s = 0.f;
            for (int n = 0; n < 64; n++) s += ps[tid][n];
            ssum += s;
        }
        {
            int ai = 0;
            for (int t = base; t < Tt; t += 4, ai++) {
                float a = acc[ai];
                #pragma unroll
                for (int n = 0; n < 64; n++) a = fmaf(ps[t][n], Vs[n][nl], a);
                acc[ai] = a;
            }
        }
        __syncthreads();
    }
    {
        int ai = 0;
        for (int t = base; t < Tt; t += 4, ai++)
            g_Pacc[(((size_t)bh*NSEG + seg)*Tt + t)*64 + nl] = acc[ai];
        if (tid < Tt) g_Psum[((size_t)bh*NSEG + seg)*Tt + tid] = ssum;
    }
}

// ---------------- K6: combine partials -> ce [B,T,512] ----------------
__global__ __launch_bounds__(512) void k_ce() {
    int r = blockIdx.x;            // 0..167
    int b = r / Tt, t = r % Tt;
    int c = threadIdx.x;
    int h = c >> 6, d = c & 63;
    int bh = b*8 + h;
    float accv = 0.f, s = 0.f;
    for (int sg = 0; sg < NSEG; sg++) {
        accv += g_Pacc[(((size_t)bh*NSEG + sg)*Tt + t)*64 + d];
        s    += g_Psum[((size_t)bh*NSEG + sg)*Tt + t];
    }
    g_ce[(size_t)r*512 + c] = accv / s;
}

// ---------------- helper: block layernorm over 512 ----------------
__device__ void ln_row512(const float* in, float* out, const float* g, const float* bb,
                          float* red, int tid) {
    float v = in[tid];
    float s = v, sq = v*v;
    for (int o = 16; o; o >>= 1) {
        s  += __shfl_down_sync(0xffffffffu, s, o);
        sq += __shfl_down_sync(0xffffffffu, sq, o);
    }
    int wid = tid >> 5, lane = tid & 31;
    if (lane == 0) { red[wid] = s; red[16 + wid] = sq; }
    __syncthreads();
    if (tid == 0) {
        float S = 0.f, SQ = 0.f;
        for (int w = 0; w < 16; w++) { S += red[w]; SQ += red[16 + w]; }
        float m = S * (1.f/512.f);
        red[32] = m;
        red[33] = rsqrtf(SQ * (1.f/512.f) - m*m + EPSV);
    }
    __syncthreads();
    float m = red[32], rs = red[33];
    out[tid] = (v - m)*rs*g[tid] + bb[tid];
    __syncthreads();
}

// ---------------- K7: cls path (proj + MLP + LN3 + k1/q1 overwrite) ----------------
__global__ __launch_bounds__(512) void k_cls(const float* __restrict__ x,
        const float* __restrict__ proj0_w, const float* __restrict__ proj0_b,
        const float* __restrict__ g2, const float* __restrict__ b2,
        const float* __restrict__ fc1_w, const float* __restrict__ fc1_b,
        const float* __restrict__ fc2_w, const float* __restrict__ fc2_b,
        const float* __restrict__ g3, const float* __restrict__ b3,
        const float* __restrict__ kv1_w, const float* __restrict__ q1_w) {
    __shared__ float cer[2][512];
    __shared__ float cls[2][512];
    __shared__ float yb[2][512];
    __shared__ float hb[2][2048];
    __shared__ float red[40];
    int tid = threadIdx.x;
    int rows[2] = {blockIdx.x*2, blockIdx.x*2 + 1};

    for (int i = 0; i < 2; i++) cer[i][tid] = g_ce[(size_t)rows[i]*512 + tid];
    __syncthreads();
    // proj0 + residual
    for (int i = 0; i < 2; i++) {
        int b = rows[i] / Tt, t = rows[i] % Tt;
        float acc = proj0_b[tid];
        for (int k = 0; k < 512; k++) acc = fmaf(cer[i][k], proj0_w[(size_t)k*512 + tid], acc);
        cls[i][tid] = x[((size_t)b*Ntok + t)*512 + tid] + acc;
    }
    __syncthreads();
    // LN2
    for (int i = 0; i < 2; i++) ln_row512(cls[i], yb[i], g2, b2, red, tid);
    // fc1 + exact gelu
    for (int i = 0; i < 2; i++)
        for (int jj = 0; jj < 4; jj++) {
            int j = tid + jj*512;
            float a = fc1_b[j];
            for (int k = 0; k < 512; k++) a = fmaf(yb[i][k], fc1_w[(size_t)k*2048 + j], a);
            hb[i][j] = 0.5f*a*(1.0f + erff(a*0.70710678118654752f));
        }
    __syncthreads();
    // fc2 + residual
    for (int i = 0; i < 2; i++) {
        float a = fc2_b[tid];
        for (int k = 0; k < 2048; k++) a = fmaf(hb[i][k], fc2_w[(size_t)k*512 + tid], a);
        cls[i][tid] += a;
    }
    __syncthreads();
    // LN3
    for (int i = 0; i < 2; i++) ln_row512(cls[i], yb[i], g3, b3, red, tid);
    // k1 overwrite (cols 0..511 of kv1_w) + q1
    for (int i = 0; i < 2; i++) {
        int b = rows[i] / Tt, t = rows[i] % Tt;
        float ak = 0.f, aq = 0.f;
        for (int k = 0; k < 512; k++) {
            float y = yb[i][k];
            ak = fmaf(y, kv1_w[(size_t)k*1024 + tid], ak);
            aq = fmaf(y, q1_w[(size_t)k*512 + tid], aq);
        }
        int h = tid >> 6, d = tid & 63;
        g_K1[(((size_t)b*Hh + h)*Ntok + t)*64 + d] = ak;
        g_q1[(size_t)rows[i]*512 + tid] = aq;
    }
}

// ---------------- K8a: final logits into d_out + segment max/sum partials ----------------
__global__ __launch_bounds__(256) void k_logits(float* __restrict__ out) {
    int bh = blockIdx.x, seg = blockIdx.y;
    int b = bh >> 3, h = bh & 7;
    __shared__ float qs[Tt][64];
    __shared__ float Ks[64][65];
    __shared__ float redm[Tt][64];
    __shared__ float reds[Tt][64];
    int tid = threadIdx.x;
    for (int i = tid; i < Tt*64; i += 256) {
        int t = i >> 6, d = i & 63;
        int flat = h*(Tt*Dd) + t*Dd + d;
        qs[t][d] = SCALEV * g_q1[(size_t)b*Tt*512 + flat];
    }
    __syncthreads();
    int base = tid >> 6, nl = tid & 63;
    float lm[6], ls[6];
    #pragma unroll
    for (int i = 0; i < 6; i++) { lm[i] = -1e30f; ls[i] = 0.f; }
    const float* Kb = g_K1 + (size_t)bh*Ntok*64;
    int n0 = seg*256;
    for (int ch = 0; ch < 4; ch++) {
        int nc = n0 + ch*64;
        for (int i = tid*4; i < 4096; i += 1024) {
            int nn = i >> 6, dd = i & 63;
            int gn = nc + nn;
            float4 kv = (gn < Ntok) ? *(const float4*)(Kb + (size_t)gn*64 + dd) : make_float4(0,0,0,0);
            Ks[nn][dd]=kv.x; Ks[nn][dd+1]=kv.y; Ks[nn][dd+2]=kv.z; Ks[nn][dd+3]=kv.w;
        }
        __syncthreads();
        int gn = nc + nl;
        bool valid = gn < Ntok;
        int ai = 0;
        for (int t = base; t < Tt; t += 4, ai++) {
            float l = 0.f;
            #pragma unroll
            for (int d = 0; d < 64; d++) l = fmaf(qs[t][d], Ks[nl][d], l);
            if (valid) {
                out[((size_t)bh*Tt + t)*Ntok + gn] = l;
                if (l > lm[ai]) { ls[ai] = ls[ai]*__expf(lm[ai] - l) + 1.f; lm[ai] = l; }
                else           { ls[ai] += __expf(l - lm[ai]); }
            }
        }
        __syncthreads();
    }
    {
        int ai = 0;
        for (int t = base; t < Tt; t += 4, ai++) { redm[t][nl] = lm[ai]; reds[t][nl] = ls[ai]; }
    }
    __syncthreads();
    if (tid < Tt) {
        float M = -1e30f, S = 0.f;
        for (int n = 0; n < 64; n++) {
            float m2 = redm[tid][n], s2 = reds[tid][n];
            if (s2 > 0.f) {
                if (m2 > M) { S = S*__expf(M - m2) + s2; M = m2; }
                else        { S += s2*__expf(m2 - M); }
            }
        }
        g_Fmax[((size_t)bh*NSEG + seg)*Tt + tid] = M;
        g_Fsum[((size_t)bh*NSEG + seg)*Tt + tid] = S;
    }
}

// ---------------- K8b: reduce partials per (bh,t) ----------------
__global__ void k_reduce() {
    int bh = blockIdx.x;
    int t = threadIdx.x;
    if (t >= Tt) return;
    float M = -1e30f, S = 0.f;
    for (int s = 0; s < NSEG; s++) {
        float m2 = g_Fmax[((size_t)bh*NSEG + s)*Tt + t];
        float s2 = g_Fsum[((size_t)bh*NSEG + s)*Tt + t];
        if (s2 > 0.f) {
            if (m2 > M) { S = S*__expf(M - m2) + s2; M = m2; }
            else        { S += s2*__expf(m2 - M); }
        }
    }
    g_Mrow[bh*Tt + t] = M;
    g_Tinv[bh*Tt + t] = 1.f / S;
}

// ---------------- K8c: normalize logits in place ----------------
__global__ __launch_bounds__(256) void k_norm(float* __restrict__ out) {
    int row = blockIdx.y;                       // 0..1343  (= bh*T + t)
    int n = blockIdx.x*256 + threadIdx.x;
    if (n < Ntok) {
        size_t i = (size_t)row*Ntok + n;
        out[i] = __expf(out[i] - g_Mrow[row]) * g_Tinv[row];
    }
}

// ---------------- launch ----------------
extern "C" void kernel_launch(void* const* d_in, const int* in_sizes, int n_in,
                              void* d_out, int out_size) {
    const float* x       = (const float*)d_in[0];
    const float* ln1_g   = (const float*)d_in[1];
    const float* ln1_b   = (const float*)d_in[2];
    const float* kv0_w   = (const float*)d_in[3];
    const float* q0_w    = (const float*)d_in[4];
    const float* proj0_w = (const float*)d_in[5];
    const float* proj0_b = (const float*)d_in[6];
    const float* ln2_g   = (const float*)d_in[7];
    const float* ln2_b   = (const float*)d_in[8];
    const float* fc1_w   = (const float*)d_in[9];
    const float* fc1_b   = (const float*)d_in[10];
    const float* fc2_w   = (const float*)d_in[11];
    const float* fc2_b   = (const float*)d_in[12];
    const float* ln3_g   = (const float*)d_in[13];
    const float* ln3_b   = (const float*)d_in[14];
    const float* kv1_w   = (const float*)d_in[15];
    const float* q1_w    = (const float*)d_in[16];
    float* out = (float*)d_out;

    k_prep<<<6, 256>>>(kv0_w, kv1_w, ln1_g, ln1_b, ln3_g, ln3_b);
    k_stats<<<(M_ROWS + 7)/8, dim3(32, 8)>>>(x);
    k_gemm<<<dim3(12, (M_ROWS + 127)/128), 256>>>(x);
    k_q0<<<Bq*Tt, 512>>>(x, q0_w, ln1_g, ln1_b);
    k_attn0<<<dim3(Bq*Hh, NSEG), 256>>>();
    k_ce<<<Bq*Tt, 512>>>();
    k_cls<<<(Bq*Tt)/2, 512>>>(x, proj0_w, proj0_b, ln2_g, ln2_b,
                              fc1_w, fc1_b, fc2_w, fc2_b, ln3_g, ln3_b, kv1_w, q1_w);
    k_logits<<<dim3(Bq*Hh, NSEG), 256>>>(out);
    k_reduce<<<Bq*Hh, 32>>>();
    k_norm<<<dim3((Ntok + 255)/256, Bq*Hh*Tt), 256>>>(out);
}

// round 3
// speedup vs baseline: 1.3300x; 1.3300x over previous
#include <cuda_runtime.h>
#include <cstdint>
#include <math.h>

#define Bq 8
#define Ntok 9237
#define Cc 512
#define Tt 21
#define Hh 8
#define Dd 64
#define HIDN 2048
#define M_ROWS (Bq*Ntok)          // 73896
#define EPSV 1e-5f
#define SCALEV 0.125f
#define NSEG 37                    // ceil(9237/256)

// ---------------- static scratch (no allocations allowed) ----------------
__device__ __align__(16) float g_mean[M_ROWS];
__device__ __align__(16) float g_rstd[M_ROWS];
__device__ __align__(16) float g_Bfrag[1536*512];   // fragment-packed, gamma-folded, tf32
__device__ __align__(16) float g_biasc[1536];
__device__ __align__(16) float g_K0[(size_t)Bq*Hh*Ntok*Dd];
__device__ __align__(16) float g_V0[(size_t)Bq*Hh*Ntok*Dd];
__device__ __align__(16) float g_K1[(size_t)Bq*Hh*Ntok*Dd];
__device__ __align__(16) float g_q0[Bq*Tt*Cc];
__device__ __align__(16) float g_q1[Bq*Tt*Cc];
__device__ __align__(16) float g_Pacc[(size_t)Bq*Hh*NSEG*Tt*Dd];
__device__ __align__(16) float g_Psum[Bq*Hh*NSEG*Tt];
__device__ __align__(16) float g_ce[Bq*Tt*Cc];
__device__ __align__(16) float g_Fmax[Bq*Hh*NSEG*Tt];
__device__ __align__(16) float g_Fsum[Bq*Hh*NSEG*Tt];
__device__ __align__(16) float g_Mrow[Bq*Hh*Tt];
__device__ __align__(16) float g_Tinv[Bq*Hh*Tt];

// ---------------- helpers ----------------
__device__ __forceinline__ uint32_t smem_u32(const void* p) {
    uint32_t a;
    asm("{ .reg .u64 t; cvta.to.shared.u64 t, %1; cvt.u32.u64 %0, t; }" : "=r"(a) : "l"(p));
    return a;
}
__device__ __forceinline__ uint32_t tf32r(float f) {
    uint32_t u; asm("cvt.rna.tf32.f32 %0, %1;" : "=r"(u) : "f"(f)); return u;
}
__device__ __forceinline__ void cp_async16(uint32_t smem, const void* g) {
    asm volatile("cp.async.cg.shared.global [%0], [%1], 16;" :: "r"(smem), "l"(g));
}
#define CP_COMMIT() asm volatile("cp.async.commit_group;" ::: "memory")
#define CP_WAIT0()  asm volatile("cp.async.wait_group 0;" ::: "memory")

__device__ __forceinline__ void mma1688(float* c, const uint32_t* a, const uint32_t* b) {
    asm volatile(
        "mma.sync.aligned.m16n8k8.row.col.f32.tf32.tf32.f32 "
        "{%0,%1,%2,%3}, {%4,%5,%6,%7}, {%8,%9}, {%0,%1,%2,%3};"
        : "+f"(c[0]), "+f"(c[1]), "+f"(c[2]), "+f"(c[3])
        : "r"(a[0]), "r"(a[1]), "r"(a[2]), "r"(a[3]), "r"(b[0]), "r"(b[1]));
}

// ---------------- K1: prep fragment-packed fused weights + folded bias ----------------
// g_Bfrag layout: [(bx*16 + chunk)*4096 + ((n8*4 + ks)*32 + lane)*2 + reg]
//   value = W[n][k]*gamma[k] (tf32), n = bx*128 + n8*8 + (lane>>2),
//   k = chunk*32 + ks*8 + (lane&3) + reg*4
__global__ __launch_bounds__(256) void k_prep(const float* __restrict__ kv0_w,
                                              const float* __restrict__ kv1_w,
                                              const float* __restrict__ g1, const float* __restrict__ b1,
                                              const float* __restrict__ g3, const float* __restrict__ b3) {
    int n = blockIdx.x;          // 0..1535
    const float *W, *g, *b; int col;
    if (n < 1024) { W = kv0_w; g = g1; b = b1; col = n; }
    else          { W = kv1_w; g = g3; b = b3; col = n - 1024; }
    int bx = n >> 7;
    int np = n & 127;
    int n8 = np >> 3, gg = np & 7;
    float partial = 0.f;
    for (int k = threadIdx.x; k < 512; k += 256) {
        float w = W[(size_t)k*1024 + col] * g[k];
        int c  = k >> 5;
        int kc = k & 31;
        int ks = kc >> 3, kin = kc & 7;
        int t = kin & 3, reg = kin >> 2;
        int lane = gg*4 + t;
        size_t idx = (size_t)(bx*16 + c)*4096 + ((n8*4 + ks)*32 + lane)*2 + reg;
        g_Bfrag[idx] = __uint_as_float(tf32r(w));
        partial += b[k] * w;
    }
    __shared__ float red[256];
    red[threadIdx.x] = partial; __syncthreads();
    for (int s = 128; s; s >>= 1) {
        if (threadIdx.x < s) red[threadIdx.x] += red[threadIdx.x + s];
        __syncthreads();
    }
    if (threadIdx.x == 0) g_biasc[n] = red[0];
}

// ---------------- K2: per-row LN stats ----------------
__global__ void k_stats(const float* __restrict__ x) {
    int row = blockIdx.x * 8 + threadIdx.y;
    if (row >= M_ROWS) return;
    const float4* xr = (const float4*)(x + (size_t)row*512);
    float s = 0.f, sq = 0.f;
    for (int i = threadIdx.x; i < 128; i += 32) {
        float4 v = xr[i];
        s  += v.x + v.y + v.z + v.w;
        sq += v.x*v.x + v.y*v.y + v.z*v.z + v.w*v.w;
    }
    for (int o = 16; o; o >>= 1) {
        s  += __shfl_down_sync(0xffffffffu, s, o);
        sq += __shfl_down_sync(0xffffffffu, sq, o);
    }
    if (threadIdx.x == 0) {
        float m = s * (1.f/512.f);
        float var = sq * (1.f/512.f) - m*m;
        g_mean[row] = m;
        g_rstd[row] = rsqrtf(var + EPSV);
    }
}

// ---------------- K3: fused LN + tf32 mma.sync GEMM ----------------
// CTA 128x128, 8 warps (2x4), warp tile 64x32, K chunk 32 double-buffered.
// As: [buf][128][36] (pad 36 -> conflict-free frag LDS), Bs: [buf][4096] frag order.
#define ASTRIDE 36
#define GEMM_SMEM ((2*128*ASTRIDE + 2*4096)*4)

__global__ __launch_bounds__(256, 2) void k_gemm_mma(const float* __restrict__ x) {
    extern __shared__ float dsm[];
    float* As = dsm;                         // 2 * 4608
    float* Bs = dsm + 2*128*ASTRIDE;         // 2 * 4096

    const int tid = threadIdx.x;
    const int bx = blockIdx.x;               // 0..11 (N tiles)
    const int by = blockIdx.y;               // 0..577 (M tiles)
    const int rowBase = by * 128;
    const int colBase = bx * 128;

    const int lane = tid & 31, wid = tid >> 5;
    const int warp_m = wid & 1, warp_n = wid >> 1;
    const int g = lane >> 2, t4 = lane & 3;

    // global A row assignment: slot = tid + it*256; r = slot>>3; q = slot&7
    const float* aptr[4];
    float meanv[4], rstdv[4];
    bool rok[4];
    int arow[4];
    #pragma unroll
    for (int it = 0; it < 4; it++) {
        int slot = tid + it*256;
        int rl = slot >> 3, q = slot & 7;
        int r = rowBase + rl;
        arow[it] = rl;
        rok[it] = (r < M_ROWS);
        aptr[it] = x + (size_t)(rok[it] ? r : 0)*512 + q*4;
        meanv[it] = rok[it] ? g_mean[r] : 0.f;
        rstdv[it] = rok[it] ? g_rstd[r] : 0.f;
    }
    const int aq4[1] = {0};
    (void)aq4;

    float acc[4][4][4];
    #pragma unroll
    for (int i = 0; i < 4; i++)
        #pragma unroll
        for (int j = 0; j < 4; j++)
            #pragma unroll
            for (int k = 0; k < 4; k++) acc[i][j][k] = 0.f;

    const float* bsrc = g_Bfrag + (size_t)bx*16*4096;
    uint32_t bs_base_u32[2];
    bs_base_u32[0] = smem_u32(Bs);
    bs_base_u32[1] = smem_u32(Bs + 4096);

    float4 astage[4];
    auto ldA = [&](int c) {
        #pragma unroll
        for (int it = 0; it < 4; it++)
            astage[it] = rok[it] ? *(const float4*)(aptr[it] + c*32) : make_float4(0,0,0,0);
    };
    auto stA = [&](int buf) {
        float* dst = As + buf*128*ASTRIDE;
        #pragma unroll
        for (int it = 0; it < 4; it++) {
            int slot = tid + it*256;
            int rl = slot >> 3, q = slot & 7;
            float m = meanv[it], s = rstdv[it];
            float4 v = astage[it];
            float4 o;
            o.x = __uint_as_float(tf32r((v.x - m)*s));
            o.y = __uint_as_float(tf32r((v.y - m)*s));
            o.z = __uint_as_float(tf32r((v.z - m)*s));
            o.w = __uint_as_float(tf32r((v.w - m)*s));
            *(float4*)(dst + rl*ASTRIDE + q*4) = o;
        }
    };
    auto ldB = [&](int c, int buf) {
        const float* src = bsrc + (size_t)c*4096;
        #pragma unroll
        for (int it = 0; it < 4; it++) {
            int off = (tid + it*256)*4;
            cp_async16(bs_base_u32[buf] + off*4, src + off);
        }
        CP_COMMIT();
    };

    // prologue
    ldA(0); stA(0); ldB(0, 0);
    CP_WAIT0();
    __syncthreads();

    int buf = 0;
    for (int c = 0; c < 16; c++) {
        if (c < 15) { ldB(c + 1, buf ^ 1); ldA(c + 1); }

        const uint32_t* Asu = (const uint32_t*)(As + buf*128*ASTRIDE);
        const uint32_t* Bsu = (const uint32_t*)(Bs + buf*4096);
        #pragma unroll
        for (int ks = 0; ks < 4; ks++) {
            uint32_t bfr[4][2];
            #pragma unroll
            for (int nf = 0; nf < 4; nf++) {
                int n8 = warp_n*4 + nf;
                int fi = ((n8*4 + ks)*32 + lane)*2;
                bfr[nf][0] = Bsu[fi];
                bfr[nf][1] = Bsu[fi + 1];
            }
            #pragma unroll
            for (int mf = 0; mf < 4; mf++) {
                int m0 = warp_m*64 + mf*16;
                int abase = (m0 + g)*ASTRIDE + ks*8 + t4;
                uint32_t afr[4];
                afr[0] = Asu[abase];
                afr[1] = Asu[abase + 8*ASTRIDE];
                afr[2] = Asu[abase + 4];
                afr[3] = Asu[abase + 8*ASTRIDE + 4];
                #pragma unroll
                for (int nf = 0; nf < 4; nf++)
                    mma1688(acc[mf][nf], afr, bfr[nf]);
            }
        }

        if (c < 15) {
            stA(buf ^ 1);
            CP_WAIT0();
            __syncthreads();
            buf ^= 1;
        }
    }

    // epilogue: scatter to K0/V0/K1 with folded bias
    const int region = bx >> 2;                // 0:K0 1:V0 2:K1
    float* dstB = (region == 0) ? g_K0 : (region == 1) ? g_V0 : g_K1;
    float2 bias[4];
    #pragma unroll
    for (int nf = 0; nf < 4; nf++) {
        int j = colBase + warp_n*32 + nf*8 + t4*2;
        bias[nf] = *(const float2*)(g_biasc + j);
    }
    #pragma unroll
    for (int mf = 0; mf < 4; mf++) {
        #pragma unroll
        for (int hi = 0; hi < 2; hi++) {
            int r = rowBase + warp_m*64 + mf*16 + g + hi*8;
            if (r >= M_ROWS) continue;
            int bb = r / Ntok, nt = r % Ntok;
            #pragma unroll
            for (int nf = 0; nf < 4; nf++) {
                int j = colBase + warp_n*32 + nf*8 + t4*2;
                int h = (j >> 6) & 7, d = j & 63;
                float2 v;
                v.x = acc[mf][nf][hi*2 + 0] + bias[nf].x;
                v.y = acc[mf][nf][hi*2 + 1] + bias[nf].y;
                *(float2*)(dstB + (((size_t)bb*Hh + h)*Ntok + nt)*64 + d) = v;
            }
        }
    }
}

// ---------------- K4: q0mat = ln1(x[:, :T]) @ q0_w ----------------
__global__ __launch_bounds__(512) void k_q0(const float* __restrict__ x,
                                            const float* __restrict__ q0_w,
                                            const float* __restrict__ g1,
                                            const float* __restrict__ b1) {
    int r = blockIdx.x;          // 0..167
    int b = r / Tt, t = r % Tt;
    int row = b*Ntok + t;
    __shared__ float y[512];
    int tid = threadIdx.x;
    float m = g_mean[row], rs = g_rstd[row];
    y[tid] = (x[(size_t)row*512 + tid] - m)*rs*g1[tid] + b1[tid];
    __syncthreads();
    float acc = 0.f;
    for (int k = 0; k < 512; k++) acc = fmaf(y[k], q0_w[(size_t)k*512 + tid], acc);
    g_q0[(size_t)r*512 + tid] = acc;
}

// ---------------- K5: attn0 partial (flash-style, unnormalized) ----------------
__global__ __launch_bounds__(256) void k_attn0() {
    int bh = blockIdx.x, seg = blockIdx.y;
    int b = bh >> 3, h = bh & 7;
    __shared__ float qs[Tt][64];
    __shared__ float Ks[64][65];
    __shared__ float Vs[64][65];
    __shared__ float ps[Tt][64];
    int tid = threadIdx.x;
    for (int i = tid; i < Tt*64; i += 256) {
        int t = i >> 6, d = i & 63;
        int flat = h*(Tt*Dd) + t*Dd + d;      // non-standard CaiT reshape
        qs[t][d] = SCALEV * g_q0[(size_t)b*Tt*512 + flat];
    }
    __syncthreads();
    int base = tid >> 6, nl = tid & 63;
    float acc[6] = {0,0,0,0,0,0};
    float ssum = 0.f;
    const float* Kb = g_K0 + (size_t)bh*Ntok*64;
    const float* Vb = g_V0 + (size_t)bh*Ntok*64;
    int n0 = seg*256;
    for (int ch = 0; ch < 4; ch++) {
        int nc = n0 + ch*64;
        for (int i = tid*4; i < 4096; i += 1024) {
            int nn = i >> 6, dd = i & 63;
            int gn = nc + nn;
            float4 kv = (gn < Ntok) ? *(const float4*)(Kb + (size_t)gn*64 + dd) : make_float4(0,0,0,0);
            float4 vv = (gn < Ntok) ? *(const float4*)(Vb + (size_t)gn*64 + dd) : make_float4(0,0,0,0);
            Ks[nn][dd]=kv.x; Ks[nn][dd+1]=kv.y; Ks[nn][dd+2]=kv.z; Ks[nn][dd+3]=kv.w;
            Vs[nn][dd]=vv.x; Vs[nn][dd+1]=vv.y; Vs[nn][dd+2]=vv.z; Vs[nn][dd+3]=vv.w;
        }
        __syncthreads();
        bool valid = (nc + nl) < Ntok;
        for (int t = base; t < Tt; t += 4) {
            float l = 0.f;
            #pragma unroll
            for (int d = 0; d < 64; d++) l = fmaf(qs[t][d], Ks[nl][d], l);
            ps[t][nl] = valid ? __expf(l) : 0.f;
        }
        __syncthreads();
        if (tid < Tt) {
            float s = 0.f;
            for (int n = 0; n < 64; n++) s += ps[tid][n];
            ssum += s;
        }
        {
            int ai = 0;
            for (int t = base; t < Tt; t += 4, ai++) {
                float a = acc[ai];
                #pragma unroll
                for (int n = 0; n < 64; n++) a = fmaf(ps[t][n], Vs[n][nl], a);
                acc[ai] = a;
            }
        }
        __syncthreads();
    }
    {
        int ai = 0;
        for (int t = base; t < Tt; t += 4, ai++)
            g_Pacc[(((size_t)bh*NSEG + seg)*Tt + t)*64 + nl] = acc[ai];
        if (tid < Tt) g_Psum[((size_t)bh*NSEG + seg)*Tt + tid] = ssum;
    }
}

// ---------------- K6: combine partials -> ce [B,T,512] ----------------
__global__ __launch_bounds__(512) void k_ce() {
    int r = blockIdx.x;            // 0..167
    int b = r / Tt, t = r % Tt;
    int c = threadIdx.x;
    int h = c >> 6, d = c & 63;
    int bh = b*8 + h;
    float accv = 0.f, s = 0.f;
    for (int sg = 0; sg < NSEG; sg++) {
        accv += g_Pacc[(((size_t)bh*NSEG + sg)*Tt + t)*64 + d];
        s    += g_Psum[((size_t)bh*NSEG + sg)*Tt + t];
    }
    g_ce[(size_t)r*512 + c] = accv / s;
}

// ---------------- helper: block layernorm over 512 ----------------
__device__ void ln_row512(const float* in, float* out, const float* g, const float* bb,
                          float* red, int tid) {
    float v = in[tid];
    float s = v, sq = v*v;
    for (int o = 16; o; o >>= 1) {
        s  += __shfl_down_sync(0xffffffffu, s, o);
        sq += __shfl_down_sync(0xffffffffu, sq, o);
    }
    int wid = tid >> 5, lane = tid & 31;
    if (lane == 0) { red[wid] = s; red[16 + wid] = sq; }
    __syncthreads();
    if (tid == 0) {
        float S = 0.f, SQ = 0.f;
        for (int w = 0; w < 16; w++) { S += red[w]; SQ += red[16 + w]; }
        float m = S * (1.f/512.f);
        red[32] = m;
        red[33] = rsqrtf(SQ * (1.f/512.f) - m*m + EPSV);
    }
    __syncthreads();
    float m = red[32], rs = red[33];
    out[tid] = (v - m)*rs*g[tid] + bb[tid];
    __syncthreads();
}

// ---------------- K7: cls path (proj + MLP + LN3 + k1/q1 overwrite) ----------------
__global__ __launch_bounds__(512) void k_cls(const float* __restrict__ x,
        const float* __restrict__ proj0_w, const float* __restrict__ proj0_b,
        const float* __restrict__ g2, const float* __restrict__ b2,
        const float* __restrict__ fc1_w, const float* __restrict__ fc1_b,
        const float* __restrict__ fc2_w, const float* __restrict__ fc2_b,
        const float* __restrict__ g3, const float* __restrict__ b3,
        const float* __restrict__ kv1_w, const float* __restrict__ q1_w) {
    __shared__ float cer[2][512];
    __shared__ float cls[2][512];
    __shared__ float yb[2][512];
    __shared__ float hb[2][2048];
    __shared__ float red[40];
    int tid = threadIdx.x;
    int rows[2] = {blockIdx.x*2, blockIdx.x*2 + 1};

    for (int i = 0; i < 2; i++) cer[i][tid] = g_ce[(size_t)rows[i]*512 + tid];
    __syncthreads();
    // proj0 + residual
    for (int i = 0; i < 2; i++) {
        int b = rows[i] / Tt, t = rows[i] % Tt;
        float acc = proj0_b[tid];
        for (int k = 0; k < 512; k++) acc = fmaf(cer[i][k], proj0_w[(size_t)k*512 + tid], acc);
        cls[i][tid] = x[((size_t)b*Ntok + t)*512 + tid] + acc;
    }
    __syncthreads();
    // LN2
    for (int i = 0; i < 2; i++) ln_row512(cls[i], yb[i], g2, b2, red, tid);
    // fc1 + exact gelu
    for (int i = 0; i < 2; i++)
        for (int jj = 0; jj < 4; jj++) {
            int j = tid + jj*512;
            float a = fc1_b[j];
            for (int k = 0; k < 512; k++) a = fmaf(yb[i][k], fc1_w[(size_t)k*2048 + j], a);
            hb[i][j] = 0.5f*a*(1.0f + erff(a*0.70710678118654752f));
        }
    __syncthreads();
    // fc2 + residual
    for (int i = 0; i < 2; i++) {
        float a = fc2_b[tid];
        for (int k = 0; k < 2048; k++) a = fmaf(hb[i][k], fc2_w[(size_t)k*512 + tid], a);
        cls[i][tid] += a;
    }
    __syncthreads();
    // LN3
    for (int i = 0; i < 2; i++) ln_row512(cls[i], yb[i], g3, b3, red, tid);
    // k1 overwrite (cols 0..511 of kv1_w) + q1
    for (int i = 0; i < 2; i++) {
        int b = rows[i] / Tt, t = rows[i] % Tt;
        float ak = 0.f, aq = 0.f;
        for (int k = 0; k < 512; k++) {
            float y = yb[i][k];
            ak = fmaf(y, kv1_w[(size_t)k*1024 + tid], ak);
            aq = fmaf(y, q1_w[(size_t)k*512 + tid], aq);
        }
        int h = tid >> 6, d = tid & 63;
        g_K1[(((size_t)b*Hh + h)*Ntok + t)*64 + d] = ak;
        g_q1[(size_t)rows[i]*512 + tid] = aq;
    }
}

// ---------------- K8a: final logits into d_out + segment max/sum partials ----------------
__global__ __launch_bounds__(256) void k_logits(float* __restrict__ out) {
    int bh = blockIdx.x, seg = blockIdx.y;
    int b = bh >> 3, h = bh & 7;
    __shared__ float qs[Tt][64];
    __shared__ float Ks[64][65];
    __shared__ float redm[Tt][64];
    __shared__ float reds[Tt][64];
    int tid = threadIdx.x;
    for (int i = tid; i < Tt*64; i += 256) {
        int t = i >> 6, d = i & 63;
        int flat = h*(Tt*Dd) + t*Dd + d;
        qs[t][d] = SCALEV * g_q1[(size_t)b*Tt*512 + flat];
    }
    __syncthreads();
    int base = tid >> 6, nl = tid & 63;
    float lm[6], ls[6];
    #pragma unroll
    for (int i = 0; i < 6; i++) { lm[i] = -1e30f; ls[i] = 0.f; }
    const float* Kb = g_K1 + (size_t)bh*Ntok*64;
    int n0 = seg*256;
    for (int ch = 0; ch < 4; ch++) {
        int nc = n0 + ch*64;
        for (int i = tid*4; i < 4096; i += 1024) {
            int nn = i >> 6, dd = i & 63;
            int gn = nc + nn;
            float4 kv = (gn < Ntok) ? *(const float4*)(Kb + (size_t)gn*64 + dd) : make_float4(0,0,0,0);
            Ks[nn][dd]=kv.x; Ks[nn][dd+1]=kv.y; Ks[nn][dd+2]=kv.z; Ks[nn][dd+3]=kv.w;
        }
        __syncthreads();
        int gn = nc + nl;
        bool valid = gn < Ntok;
        int ai = 0;
        for (int t = base; t < Tt; t += 4, ai++) {
            float l = 0.f;
            #pragma unroll
            for (int d = 0; d < 64; d++) l = fmaf(qs[t][d], Ks[nl][d], l);
            if (valid) {
                out[((size_t)bh*Tt + t)*Ntok + gn] = l;
                if (l > lm[ai]) { ls[ai] = ls[ai]*__expf(lm[ai] - l) + 1.f; lm[ai] = l; }
                else           { ls[ai] += __expf(l - lm[ai]); }
            }
        }
        __syncthreads();
    }
    {
        int ai = 0;
        for (int t = base; t < Tt; t += 4, ai++) { redm[t][nl] = lm[ai]; reds[t][nl] = ls[ai]; }
    }
    __syncthreads();
    if (tid < Tt) {
        float M = -1e30f, S = 0.f;
        for (int n = 0; n < 64; n++) {
            float m2 = redm[tid][n], s2 = reds[tid][n];
            if (s2 > 0.f) {
                if (m2 > M) { S = S*__expf(M - m2) + s2; M = m2; }
                else        { S += s2*__expf(m2 - M); }
            }
        }
        g_Fmax[((size_t)bh*NSEG + seg)*Tt + tid] = M;
        g_Fsum[((size_t)bh*NSEG + seg)*Tt + tid] = S;
    }
}

// ---------------- K8b: reduce partials per (bh,t) ----------------
__global__ void k_reduce() {
    int bh = blockIdx.x;
    int t = threadIdx.x;
    if (t >= Tt) return;
    float M = -1e30f, S = 0.f;
    for (int s = 0; s < NSEG; s++) {
        float m2 = g_Fmax[((size_t)bh*NSEG + s)*Tt + t];
        float s2 = g_Fsum[((size_t)bh*NSEG + s)*Tt + t];
        if (s2 > 0.f) {
            if (m2 > M) { S = S*__expf(M - m2) + s2; M = m2; }
            else        { S += s2*__expf(m2 - M); }
        }
    }
    g_Mrow[bh*Tt + t] = M;
    g_Tinv[bh*Tt + t] = 1.f / S;
}

// ---------------- K8c: normalize logits in place ----------------
__global__ __launch_bounds__(256) void k_norm(float* __restrict__ out) {
    int row = blockIdx.y;                       // 0..1343  (= bh*T + t)
    int n = blockIdx.x*256 + threadIdx.x;
    if (n < Ntok) {
        size_t i = (size_t)row*Ntok + n;
        out[i] = __expf(out[i] - g_Mrow[row]) * g_Tinv[row];
    }
}

// ---------------- launch ----------------
extern "C" void kernel_launch(void* const* d_in, const int* in_sizes, int n_in,
                              void* d_out, int out_size) {
    const float* x       = (const float*)d_in[0];
    const float* ln1_g   = (const float*)d_in[1];
    const float* ln1_b   = (const float*)d_in[2];
    const float* kv0_w   = (const float*)d_in[3];
    const float* q0_w    = (const float*)d_in[4];
    const float* proj0_w = (const float*)d_in[5];
    const float* proj0_b = (const float*)d_in[6];
    const float* ln2_g   = (const float*)d_in[7];
    const float* ln2_b   = (const float*)d_in[8];
    const float* fc1_w   = (const float*)d_in[9];
    const float* fc1_b   = (const float*)d_in[10];
    const float* fc2_w   = (const float*)d_in[11];
    const float* fc2_b   = (const float*)d_in[12];
    const float* ln3_g   = (const float*)d_in[13];
    const float* ln3_b   = (const float*)d_in[14];
    const float* kv1_w   = (const float*)d_in[15];
    const float* q1_w    = (const float*)d_in[16];
    float* out = (float*)d_out;

    static int smem_set = 0;
    if (!smem_set) {
        cudaFuncSetAttribute(k_gemm_mma, cudaFuncAttributeMaxDynamicSharedMemorySize, GEMM_SMEM);
        smem_set = 1;
    }

    k_prep<<<1536, 256>>>(kv0_w, kv1_w, ln1_g, ln1_b, ln3_g, ln3_b);
    k_stats<<<(M_ROWS + 7)/8, dim3(32, 8)>>>(x);
    k_gemm_mma<<<dim3(12, 578), 256, GEMM_SMEM>>>(x);
    k_q0<<<Bq*Tt, 512>>>(x, q0_w, ln1_g, ln1_b);
    k_attn0<<<dim3(Bq*Hh, NSEG), 256>>>();
    k_ce<<<Bq*Tt, 512>>>();
    k_cls<<<(Bq*Tt)/2, 512>>>(x, proj0_w, proj0_b, ln2_g, ln2_b,
                              fc1_w, fc1_b, fc2_w, fc2_b, ln3_g, ln3_b, kv1_w, q1_w);
    k_logits<<<dim3(Bq*Hh, NSEG), 256>>>(out);
    k_reduce<<<Bq*Hh, 32>>>();
    k_norm<<<dim3((Ntok + 255)/256, Bq*Hh*Tt), 256>>>(out);
}

// round 4
// speedup vs baseline: 2.1496x; 1.6163x over previous
#include <cuda_runtime.h>
#include <cstdint>
#include <math.h>

#define Bq 8
#define Ntok 9237
#define Cc 512
#define Tt 21
#define Hh 8
#define Dd 64
#define HIDN 2048
#define M_ROWS (Bq*Ntok)          // 73896
#define EPSV 1e-5f
#define SCALEV 0.125f
#define NSEG 37                    // ceil(9237/256)
#define PSTR 72                    // smem row stride (floats): conflict-free frags

// ---------------- static scratch (no allocations allowed) ----------------
__device__ __align__(16) float g_mean[M_ROWS];
__device__ __align__(16) float g_rstd[M_ROWS];
__device__ __align__(16) float g_Bfrag[1536*512];   // fragment-packed, gamma-folded, tf32
__device__ __align__(16) float g_biasc[1536];
__device__ __align__(16) float g_K0[(size_t)Bq*Hh*Ntok*Dd];
__device__ __align__(16) float g_V0[(size_t)Bq*Hh*Ntok*Dd];
__device__ __align__(16) float g_K1[(size_t)Bq*Hh*Ntok*Dd];
__device__ __align__(16) float g_q0[Bq*Tt*Cc];
__device__ __align__(16) float g_q1[Bq*Tt*Cc];
__device__ __align__(16) float g_Pacc[(size_t)Bq*Hh*NSEG*Tt*Dd];
__device__ __align__(16) float g_Psum[Bq*Hh*NSEG*Tt];
__device__ __align__(16) float g_ce[Bq*Tt*Cc];
__device__ __align__(16) float g_Fsum[Bq*Hh*NSEG*Tt];
__device__ __align__(16) float g_Tinv[Bq*Hh*Tt];

// ---------------- helpers ----------------
__device__ __forceinline__ uint32_t smem_u32(const void* p) {
    uint32_t a;
    asm("{ .reg .u64 t; cvta.to.shared.u64 t, %1; cvt.u32.u64 %0, t; }" : "=r"(a) : "l"(p));
    return a;
}
__device__ __forceinline__ uint32_t tf32r(float f) {
    uint32_t u; asm("cvt.rna.tf32.f32 %0, %1;" : "=r"(u) : "f"(f)); return u;
}
__device__ __forceinline__ void cp_async16(uint32_t smem, const void* g) {
    asm volatile("cp.async.cg.shared.global [%0], [%1], 16;" :: "r"(smem), "l"(g));
}
__device__ __forceinline__ void cp_async16z(uint32_t smem, const void* g, int szbytes) {
    asm volatile("cp.async.cg.shared.global [%0], [%1], 16, %2;"
                 :: "r"(smem), "l"(g), "r"(szbytes));
}
#define CP_COMMIT() asm volatile("cp.async.commit_group;" ::: "memory")
#define CP_WAIT0()  asm volatile("cp.async.wait_group 0;" ::: "memory")

__device__ __forceinline__ void mma1688(float* c, const uint32_t* a, const uint32_t* b) {
    asm volatile(
        "mma.sync.aligned.m16n8k8.row.col.f32.tf32.tf32.f32 "
        "{%0,%1,%2,%3}, {%4,%5,%6,%7}, {%8,%9}, {%0,%1,%2,%3};"
        : "+f"(c[0]), "+f"(c[1]), "+f"(c[2]), "+f"(c[3])
        : "r"(a[0]), "r"(a[1]), "r"(a[2]), "r"(a[3]), "r"(b[0]), "r"(b[1]));
}

// ---------------- K1: prep fragment-packed fused weights + folded bias ----------------
__global__ __launch_bounds__(256) void k_prep(const float* __restrict__ kv0_w,
                                              const float* __restrict__ kv1_w,
                                              const float* __restrict__ g1, const float* __restrict__ b1,
                                              const float* __restrict__ g3, const float* __restrict__ b3) {
    int n = blockIdx.x;          // 0..1535
    const float *W, *g, *b; int col;
    if (n < 1024) { W = kv0_w; g = g1; b = b1; col = n; }
    else          { W = kv1_w; g = g3; b = b3; col = n - 1024; }
    int bx = n >> 7;
    int np = n & 127;
    int n8 = np >> 3, gg = np & 7;
    float partial = 0.f;
    for (int k = threadIdx.x; k < 512; k += 256) {
        float w = W[(size_t)k*1024 + col] * g[k];
        int c  = k >> 5;
        int kc = k & 31;
        int ks = kc >> 3, kin = kc & 7;
        int t = kin & 3, reg = kin >> 2;
        int lane = gg*4 + t;
        size_t idx = (size_t)(bx*16 + c)*4096 + ((n8*4 + ks)*32 + lane)*2 + reg;
        g_Bfrag[idx] = __uint_as_float(tf32r(w));
        partial += b[k] * w;
    }
    __shared__ float red[256];
    red[threadIdx.x] = partial; __syncthreads();
    for (int s = 128; s; s >>= 1) {
        if (threadIdx.x < s) red[threadIdx.x] += red[threadIdx.x + s];
        __syncthreads();
    }
    if (threadIdx.x == 0) g_biasc[n] = red[0];
}

// ---------------- K2: per-row LN stats ----------------
__global__ void k_stats(const float* __restrict__ x) {
    int row = blockIdx.x * 8 + threadIdx.y;
    if (row >= M_ROWS) return;
    const float4* xr = (const float4*)(x + (size_t)row*512);
    float s = 0.f, sq = 0.f;
    for (int i = threadIdx.x; i < 128; i += 32) {
        float4 v = xr[i];
        s  += v.x + v.y + v.z + v.w;
        sq += v.x*v.x + v.y*v.y + v.z*v.z + v.w*v.w;
    }
    for (int o = 16; o; o >>= 1) {
        s  += __shfl_down_sync(0xffffffffu, s, o);
        sq += __shfl_down_sync(0xffffffffu, sq, o);
    }
    if (threadIdx.x == 0) {
        float m = s * (1.f/512.f);
        float var = sq * (1.f/512.f) - m*m;
        g_mean[row] = m;
        g_rstd[row] = rsqrtf(var + EPSV);
    }
}

// ---------------- K3: fused LN + tf32 mma.sync GEMM ----------------
#define ASTRIDE 36
#define GEMM_SMEM ((2*128*ASTRIDE + 2*4096)*4)

__global__ __launch_bounds__(256, 2) void k_gemm_mma(const float* __restrict__ x) {
    extern __shared__ float dsm[];
    float* As = dsm;
    float* Bs = dsm + 2*128*ASTRIDE;

    const int tid = threadIdx.x;
    const int bx = blockIdx.x;
    const int by = blockIdx.y;
    const int rowBase = by * 128;
    const int colBase = bx * 128;

    const int lane = tid & 31, wid = tid >> 5;
    const int warp_m = wid & 1, warp_n = wid >> 1;
    const int g = lane >> 2, t4 = lane & 3;

    const float* aptr[4];
    float meanv[4], rstdv[4];
    bool rok[4];
    #pragma unroll
    for (int it = 0; it < 4; it++) {
        int slot = tid + it*256;
        int rl = slot >> 3, q = slot & 7;
        int r = rowBase + rl;
        rok[it] = (r < M_ROWS);
        aptr[it] = x + (size_t)(rok[it] ? r : 0)*512 + q*4;
        meanv[it] = rok[it] ? g_mean[r] : 0.f;
        rstdv[it] = rok[it] ? g_rstd[r] : 0.f;
    }

    float acc[4][4][4];
    #pragma unroll
    for (int i = 0; i < 4; i++)
        #pragma unroll
        for (int j = 0; j < 4; j++)
            #pragma unroll
            for (int k = 0; k < 4; k++) acc[i][j][k] = 0.f;

    const float* bsrc = g_Bfrag + (size_t)bx*16*4096;
    uint32_t bs_base_u32[2];
    bs_base_u32[0] = smem_u32(Bs);
    bs_base_u32[1] = smem_u32(Bs + 4096);

    float4 astage[4];
    auto ldA = [&](int c) {
        #pragma unroll
        for (int it = 0; it < 4; it++)
            astage[it] = rok[it] ? *(const float4*)(aptr[it] + c*32) : make_float4(0,0,0,0);
    };
    auto stA = [&](int buf) {
        float* dst = As + buf*128*ASTRIDE;
        #pragma unroll
        for (int it = 0; it < 4; it++) {
            int slot = tid + it*256;
            int rl = slot >> 3, q = slot & 7;
            float m = meanv[it], s = rstdv[it];
            float4 v = astage[it];
            float4 o;
            o.x = __uint_as_float(tf32r((v.x - m)*s));
            o.y = __uint_as_float(tf32r((v.y - m)*s));
            o.z = __uint_as_float(tf32r((v.z - m)*s));
            o.w = __uint_as_float(tf32r((v.w - m)*s));
            *(float4*)(dst + rl*ASTRIDE + q*4) = o;
        }
    };
    auto ldB = [&](int c, int buf) {
        const float* src = bsrc + (size_t)c*4096;
        #pragma unroll
        for (int it = 0; it < 4; it++) {
            int off = (tid + it*256)*4;
            cp_async16(bs_base_u32[buf] + off*4, src + off);
        }
        CP_COMMIT();
    };

    ldA(0); stA(0); ldB(0, 0);
    CP_WAIT0();
    __syncthreads();

    int buf = 0;
    for (int c = 0; c < 16; c++) {
        if (c < 15) { ldB(c + 1, buf ^ 1); ldA(c + 1); }

        const uint32_t* Asu = (const uint32_t*)(As + buf*128*ASTRIDE);
        const uint32_t* Bsu = (const uint32_t*)(Bs + buf*4096);
        #pragma unroll
        for (int ks = 0; ks < 4; ks++) {
            uint32_t bfr[4][2];
            #pragma unroll
            for (int nf = 0; nf < 4; nf++) {
                int n8 = warp_n*4 + nf;
                int fi = ((n8*4 + ks)*32 + lane)*2;
                bfr[nf][0] = Bsu[fi];
                bfr[nf][1] = Bsu[fi + 1];
            }
            #pragma unroll
            for (int mf = 0; mf < 4; mf++) {
                int m0 = warp_m*64 + mf*16;
                int abase = (m0 + g)*ASTRIDE + ks*8 + t4;
                uint32_t afr[4];
                afr[0] = Asu[abase];
                afr[1] = Asu[abase + 8*ASTRIDE];
                afr[2] = Asu[abase + 4];
                afr[3] = Asu[abase + 8*ASTRIDE + 4];
                #pragma unroll
                for (int nf = 0; nf < 4; nf++)
                    mma1688(acc[mf][nf], afr, bfr[nf]);
            }
        }

        if (c < 15) {
            stA(buf ^ 1);
            CP_WAIT0();
            __syncthreads();
            buf ^= 1;
        }
    }

    const int region = bx >> 2;
    float* dstB = (region == 0) ? g_K0 : (region == 1) ? g_V0 : g_K1;
    float2 bias[4];
    #pragma unroll
    for (int nf = 0; nf < 4; nf++) {
        int j = colBase + warp_n*32 + nf*8 + t4*2;
        bias[nf] = *(const float2*)(g_biasc + j);
    }
    #pragma unroll
    for (int mf = 0; mf < 4; mf++) {
        #pragma unroll
        for (int hi = 0; hi < 2; hi++) {
            int r = rowBase + warp_m*64 + mf*16 + g + hi*8;
            if (r >= M_ROWS) continue;
            int bb = r / Ntok, nt = r % Ntok;
            #pragma unroll
            for (int nf = 0; nf < 4; nf++) {
                int j = colBase + warp_n*32 + nf*8 + t4*2;
                int h = (j >> 6) & 7, d = j & 63;
                float2 v;
                v.x = acc[mf][nf][hi*2 + 0] + bias[nf].x;
                v.y = acc[mf][nf][hi*2 + 1] + bias[nf].y;
                *(float2*)(dstB + (((size_t)bb*Hh + h)*Ntok + nt)*64 + d) = v;
            }
        }
    }
}

// ---------------- K4: q0mat = ln1(x[:, :T]) @ q0_w ----------------
__global__ __launch_bounds__(512) void k_q0(const float* __restrict__ x,
                                            const float* __restrict__ q0_w,
                                            const float* __restrict__ g1,
                                            const float* __restrict__ b1) {
    int r = blockIdx.x;
    int b = r / Tt, t = r % Tt;
    int row = b*Ntok + t;
    __shared__ float y[512];
    int tid = threadIdx.x;
    float m = g_mean[row], rs = g_rstd[row];
    y[tid] = (x[(size_t)row*512 + tid] - m)*rs*g1[tid] + b1[tid];
    __syncthreads();
    float acc = 0.f;
    for (int k = 0; k < 512; k++) acc = fmaf(y[k], q0_w[(size_t)k*512 + tid], acc);
    g_q0[(size_t)r*512 + tid] = acc;
}

// ---------------- K5: attn0 via mma (QK -> exp -> PV), unnormalized partials ----
#define ATT_SMEM ((32*PSTR + 64*PSTR + 64*PSTR + 32*PSTR)*4 + 8*32*4)

__global__ __launch_bounds__(256) void k_attn0_mma() {
    extern __shared__ float sm[];
    float* Qs = sm;                      // [32][PSTR]
    float* Ks = Qs + 32*PSTR;            // [64][PSTR]
    float* Vs = Ks + 64*PSTR;            // [64][PSTR]
    float* Ps = Vs + 64*PSTR;            // [32][PSTR]
    float* ws = Ps + 32*PSTR;            // [8][32]

    int bh = blockIdx.x, seg = blockIdx.y;
    int b = bh >> 3, h = bh & 7;
    int tid = threadIdx.x;
    int lane = tid & 31, w = tid >> 5;
    int g = lane >> 2, t4 = lane & 3;

    // Q: rows 0..20 valid, rest zero; SCALE folded; rna-round
    for (int i = tid; i < 32*64; i += 256) {
        int t = i >> 6, d = i & 63;
        float v = (t < Tt) ? SCALEV * g_q0[(size_t)b*Tt*512 + h*(Tt*Dd) + t*Dd + d] : 0.f;
        Qs[t*PSTR + d] = __uint_as_float(tf32r(v));
    }
    __syncthreads();

    const float* Kb = g_K0 + (size_t)bh*Ntok*64;
    const float* Vb = g_V0 + (size_t)bh*Ntok*64;
    uint32_t KsU = smem_u32(Ks), VsU = smem_u32(Vs);

    float o[2][4];
    #pragma unroll
    for (int m = 0; m < 2; m++)
        #pragma unroll
        for (int e = 0; e < 4; e++) o[m][e] = 0.f;
    float ssum[4] = {0.f, 0.f, 0.f, 0.f};

    for (int ch = 0; ch < 4; ch++) {
        int nc = seg*256 + ch*64;
        // load K,V chunk via cp.async (zero-fill OOB)
        #pragma unroll
        for (int it = 0; it < 4; it++) {
            int slot = tid + it*256;
            int r = slot >> 4, c4 = (slot & 15)*4;
            int gn = nc + r;
            bool p = gn < Ntok;
            int gc = p ? gn : 0;
            int sz = p ? 16 : 0;
            cp_async16z(KsU + (r*PSTR + c4)*4, Kb + (size_t)gc*64 + c4, sz);
            cp_async16z(VsU + (r*PSTR + c4)*4, Vb + (size_t)gc*64 + c4, sz);
        }
        CP_COMMIT(); CP_WAIT0();
        __syncthreads();

        // QK: S[32 rows][64 token cols]; warp w -> token cols w*8..w*8+7
        float s[2][4];
        #pragma unroll
        for (int m = 0; m < 2; m++)
            #pragma unroll
            for (int e = 0; e < 4; e++) s[m][e] = 0.f;
        #pragma unroll
        for (int ks = 0; ks < 8; ks++) {
            uint32_t bfr[2];
            bfr[0] = __float_as_uint(Ks[(w*8 + g)*PSTR + ks*8 + t4]);
            bfr[1] = __float_as_uint(Ks[(w*8 + g)*PSTR + ks*8 + t4 + 4]);
            #pragma unroll
            for (int m = 0; m < 2; m++) {
                uint32_t afr[4];
                int ab = (m*16 + g)*PSTR + ks*8 + t4;
                afr[0] = __float_as_uint(Qs[ab]);
                afr[1] = __float_as_uint(Qs[ab + 8*PSTR]);
                afr[2] = __float_as_uint(Qs[ab + 4]);
                afr[3] = __float_as_uint(Qs[ab + 8*PSTR + 4]);
                mma1688(s[m], afr, bfr);
            }
        }

        // exp + mask + store P + row sums
        int tok0 = nc + w*8 + 2*t4;
        int tok1 = tok0 + 1;
        #pragma unroll
        for (int m = 0; m < 2; m++) {
            float e0 = __expf(s[m][0]), e1 = __expf(s[m][1]);
            float e2 = __expf(s[m][2]), e3 = __expf(s[m][3]);
            if (tok0 >= Ntok) { e0 = 0.f; e2 = 0.f; }
            if (tok1 >= Ntok) { e1 = 0.f; e3 = 0.f; }
            e0 = __uint_as_float(tf32r(e0)); e1 = __uint_as_float(tf32r(e1));
            e2 = __uint_as_float(tf32r(e2)); e3 = __uint_as_float(tf32r(e3));
            float2 p01 = make_float2(e0, e1), p23 = make_float2(e2, e3);
            *(float2*)&Ps[(m*16 + g)*PSTR + w*8 + 2*t4] = p01;
            *(float2*)&Ps[(m*16 + g + 8)*PSTR + w*8 + 2*t4] = p23;
            float r0 = e0 + e1, r1 = e2 + e3;
            r0 += __shfl_xor_sync(0xffffffffu, r0, 1);
            r0 += __shfl_xor_sync(0xffffffffu, r0, 2);
            r1 += __shfl_xor_sync(0xffffffffu, r1, 1);
            r1 += __shfl_xor_sync(0xffffffffu, r1, 2);
            if (t4 == 0) { ssum[m*2] += r0; ssum[m*2 + 1] += r1; }
        }
        __syncthreads();

        // PV: O[32][64] += P[32][64tok] * V[64tok][64d]; warp w -> dims w*8..w*8+7
        #pragma unroll
        for (int ks = 0; ks < 8; ks++) {
            uint32_t bfr[2];
            bfr[0] = __float_as_uint(Vs[(ks*8 + t4)*PSTR + w*8 + g]);
            bfr[1] = __float_as_uint(Vs[(ks*8 + t4 + 4)*PSTR + w*8 + g]);
            #pragma unroll
            for (int m = 0; m < 2; m++) {
                uint32_t afr[4];
                int ab = (m*16 + g)*PSTR + ks*8 + t4;
                afr[0] = __float_as_uint(Ps[ab]);
                afr[1] = __float_as_uint(Ps[ab + 8*PSTR]);
                afr[2] = __float_as_uint(Ps[ab + 4]);
                afr[3] = __float_as_uint(Ps[ab + 8*PSTR + 4]);
                mma1688(o[m], afr, bfr);
            }
        }
        __syncthreads();
    }

    // reduce row sums across warps
    if (t4 == 0) {
        ws[w*32 + g]      = ssum[0];
        ws[w*32 + g + 8]  = ssum[1];
        ws[w*32 + 16 + g] = ssum[2];
        ws[w*32 + 24 + g] = ssum[3];
    }
    __syncthreads();
    if (tid < Tt) {
        float s = 0.f;
        #pragma unroll
        for (int wq = 0; wq < 8; wq++) s += ws[wq*32 + tid];
        g_Psum[((size_t)bh*NSEG + seg)*Tt + tid] = s;
    }

    // write O partials (rows < Tt)
    #pragma unroll
    for (int m = 0; m < 2; m++) {
        int r0 = m*16 + g, r1 = m*16 + g + 8;
        int d0 = w*8 + 2*t4;
        if (r0 < Tt)
            *(float2*)&g_Pacc[(((size_t)bh*NSEG + seg)*Tt + r0)*64 + d0] =
                make_float2(o[m][0], o[m][1]);
        if (r1 < Tt)
            *(float2*)&g_Pacc[(((size_t)bh*NSEG + seg)*Tt + r1)*64 + d0] =
                make_float2(o[m][2], o[m][3]);
    }
}

// ---------------- K6: combine partials -> ce [B,T,512] ----------------
__global__ __launch_bounds__(512) void k_ce() {
    int r = blockIdx.x;
    int b = r / Tt, t = r % Tt;
    int c = threadIdx.x;
    int h = c >> 6, d = c & 63;
    int bh = b*8 + h;
    float accv = 0.f, s = 0.f;
    for (int sg = 0; sg < NSEG; sg++) {
        accv += g_Pacc[(((size_t)bh*NSEG + sg)*Tt + t)*64 + d];
        s    += g_Psum[((size_t)bh*NSEG + sg)*Tt + t];
    }
    g_ce[(size_t)r*512 + c] = accv / s;
}

// ---------------- helper: block layernorm over 512 ----------------
__device__ void ln_row512(const float* in, float* out, const float* g, const float* bb,
                          float* red, int tid) {
    float v = in[tid];
    float s = v, sq = v*v;
    for (int o = 16; o; o >>= 1) {
        s  += __shfl_down_sync(0xffffffffu, s, o);
        sq += __shfl_down_sync(0xffffffffu, sq, o);
    }
    int wid = tid >> 5, lane = tid & 31;
    if (lane == 0) { red[wid] = s; red[16 + wid] = sq; }
    __syncthreads();
    if (tid == 0) {
        float S = 0.f, SQ = 0.f;
        for (int w = 0; w < 16; w++) { S += red[w]; SQ += red[16 + w]; }
        float m = S * (1.f/512.f);
        red[32] = m;
        red[33] = rsqrtf(SQ * (1.f/512.f) - m*m + EPSV);
    }
    __syncthreads();
    float m = red[32], rs = red[33];
    out[tid] = (v - m)*rs*g[tid] + bb[tid];
    __syncthreads();
}

// ---------------- K7: cls path (proj + MLP + LN3 + k1/q1 overwrite) ----------------
__global__ __launch_bounds__(512) void k_cls(const float* __restrict__ x,
        const float* __restrict__ proj0_w, const float* __restrict__ proj0_b,
        const float* __restrict__ g2, const float* __restrict__ b2,
        const float* __restrict__ fc1_w, const float* __restrict__ fc1_b,
        const float* __restrict__ fc2_w, const float* __restrict__ fc2_b,
        const float* __restrict__ g3, const float* __restrict__ b3,
        const float* __restrict__ kv1_w, const float* __restrict__ q1_w) {
    __shared__ float cer[2][512];
    __shared__ float cls[2][512];
    __shared__ float yb[2][512];
    __shared__ float hb[2][2048];
    __shared__ float red[40];
    int tid = threadIdx.x;
    int rows[2] = {blockIdx.x*2, blockIdx.x*2 + 1};

    for (int i = 0; i < 2; i++) cer[i][tid] = g_ce[(size_t)rows[i]*512 + tid];
    __syncthreads();
    for (int i = 0; i < 2; i++) {
        int b = rows[i] / Tt, t = rows[i] % Tt;
        float acc = proj0_b[tid];
        for (int k = 0; k < 512; k++) acc = fmaf(cer[i][k], proj0_w[(size_t)k*512 + tid], acc);
        cls[i][tid] = x[((size_t)b*Ntok + t)*512 + tid] + acc;
    }
    __syncthreads();
    for (int i = 0; i < 2; i++) ln_row512(cls[i], yb[i], g2, b2, red, tid);
    for (int i = 0; i < 2; i++)
        for (int jj = 0; jj < 4; jj++) {
            int j = tid + jj*512;
            float a = fc1_b[j];
            for (int k = 0; k < 512; k++) a = fmaf(yb[i][k], fc1_w[(size_t)k*2048 + j], a);
            hb[i][j] = 0.5f*a*(1.0f + erff(a*0.70710678118654752f));
        }
    __syncthreads();
    for (int i = 0; i < 2; i++) {
        float a = fc2_b[tid];
        for (int k = 0; k < 2048; k++) a = fmaf(hb[i][k], fc2_w[(size_t)k*512 + tid], a);
        cls[i][tid] += a;
    }
    __syncthreads();
    for (int i = 0; i < 2; i++) ln_row512(cls[i], yb[i], g3, b3, red, tid);
    for (int i = 0; i < 2; i++) {
        int b = rows[i] / Tt, t = rows[i] % Tt;
        float ak = 0.f, aq = 0.f;
        for (int k = 0; k < 512; k++) {
            float y = yb[i][k];
            ak = fmaf(y, kv1_w[(size_t)k*1024 + tid], ak);
            aq = fmaf(y, q1_w[(size_t)k*512 + tid], aq);
        }
        int h = tid >> 6, d = tid & 63;
        g_K1[(((size_t)b*Hh + h)*Ntok + t)*64 + d] = ak;
        g_q1[(size_t)rows[i]*512 + tid] = aq;
    }
}

// ---------------- K8a: final logits via mma + per-segment sumexp ----------------
__global__ __launch_bounds__(256) void k_logits_mma(float* __restrict__ out) {
    __shared__ float Qs[32*PSTR];
    __shared__ float Ks[64*PSTR];
    __shared__ float ws[8*32];

    int bh = blockIdx.x, seg = blockIdx.y;
    int b = bh >> 3, h = bh & 7;
    int tid = threadIdx.x;
    int lane = tid & 31, w = tid >> 5;
    int g = lane >> 2, t4 = lane & 3;

    for (int i = tid; i < 32*64; i += 256) {
        int t = i >> 6, d = i & 63;
        float v = (t < Tt) ? SCALEV * g_q1[(size_t)b*Tt*512 + h*(Tt*Dd) + t*Dd + d] : 0.f;
        Qs[t*PSTR + d] = __uint_as_float(tf32r(v));
    }
    __syncthreads();

    const float* Kb = g_K1 + (size_t)bh*Ntok*64;
    uint32_t KsU = smem_u32(Ks);
    float ssum[4] = {0.f, 0.f, 0.f, 0.f};

    for (int ch = 0; ch < 4; ch++) {
        int nc = seg*256 + ch*64;
        #pragma unroll
        for (int it = 0; it < 2; it++) {
            int slot = tid + it*256;
            int r = slot >> 3, c4 = (slot & 7)*8;   // 2 x 16B per row? no: 64 floats/row
            (void)r; (void)c4;
        }
        #pragma unroll
        for (int it = 0; it < 4; it++) {
            int slot = tid + it*256;
            int r = slot >> 4, c4 = (slot & 15)*4;
            int gn = nc + r;
            bool p = gn < Ntok;
            int gc = p ? gn : 0;
            int sz = p ? 16 : 0;
            cp_async16z(KsU + (r*PSTR + c4)*4, Kb + (size_t)gc*64 + c4, sz);
        }
        CP_COMMIT(); CP_WAIT0();
        __syncthreads();

        float s[2][4];
        #pragma unroll
        for (int m = 0; m < 2; m++)
            #pragma unroll
            for (int e = 0; e < 4; e++) s[m][e] = 0.f;
        #pragma unroll
        for (int ks = 0; ks < 8; ks++) {
            uint32_t bfr[2];
            bfr[0] = __float_as_uint(Ks[(w*8 + g)*PSTR + ks*8 + t4]);
            bfr[1] = __float_as_uint(Ks[(w*8 + g)*PSTR + ks*8 + t4 + 4]);
            #pragma unroll
            for (int m = 0; m < 2; m++) {
                uint32_t afr[4];
                int ab = (m*16 + g)*PSTR + ks*8 + t4;
                afr[0] = __float_as_uint(Qs[ab]);
                afr[1] = __float_as_uint(Qs[ab + 8*PSTR]);
                afr[2] = __float_as_uint(Qs[ab + 4]);
                afr[3] = __float_as_uint(Qs[ab + 8*PSTR + 4]);
                mma1688(s[m], afr, bfr);
            }
        }

        int tok0 = nc + w*8 + 2*t4;
        int tok1 = tok0 + 1;
        #pragma unroll
        for (int m = 0; m < 2; m++) {
            int r0 = m*16 + g, r1 = m*16 + g + 8;
            if (r0 < Tt) {
                size_t ob = ((size_t)bh*Tt + r0)*Ntok;
                if (tok0 < Ntok) out[ob + tok0] = s[m][0];
                if (tok1 < Ntok) out[ob + tok1] = s[m][1];
            }
            if (r1 < Tt) {
                size_t ob = ((size_t)bh*Tt + r1)*Ntok;
                if (tok0 < Ntok) out[ob + tok0] = s[m][2];
                if (tok1 < Ntok) out[ob + tok1] = s[m][3];
            }
            float e0 = __expf(s[m][0]), e1 = __expf(s[m][1]);
            float e2 = __expf(s[m][2]), e3 = __expf(s[m][3]);
            if (tok0 >= Ntok) { e0 = 0.f; e2 = 0.f; }
            if (tok1 >= Ntok) { e1 = 0.f; e3 = 0.f; }
            float r0s = e0 + e1, r1s = e2 + e3;
            r0s += __shfl_xor_sync(0xffffffffu, r0s, 1);
            r0s += __shfl_xor_sync(0xffffffffu, r0s, 2);
            r1s += __shfl_xor_sync(0xffffffffu, r1s, 1);
            r1s += __shfl_xor_sync(0xffffffffu, r1s, 2);
            if (t4 == 0) { ssum[m*2] += r0s; ssum[m*2 + 1] += r1s; }
        }
        __syncthreads();
    }

    if (t4 == 0) {
        ws[w*32 + g]      = ssum[0];
        ws[w*32 + g + 8]  = ssum[1];
        ws[w*32 + 16 + g] = ssum[2];
        ws[w*32 + 24 + g] = ssum[3];
    }
    __syncthreads();
    if (tid < Tt) {
        float s = 0.f;
        #pragma unroll
        for (int wq = 0; wq < 8; wq++) s += ws[wq*32 + tid];
        g_Fsum[((size_t)bh*NSEG + seg)*Tt + tid] = s;
    }
}

// ---------------- K8b: reduce sums per (bh,t) ----------------
__global__ void k_reduce() {
    int bh = blockIdx.x;
    int t = threadIdx.x;
    if (t >= Tt) return;
    float S = 0.f;
    for (int s = 0; s < NSEG; s++)
        S += g_Fsum[((size_t)bh*NSEG + s)*Tt + t];
    g_Tinv[bh*Tt + t] = 1.f / S;
}

// ---------------- K8c: normalize logits in place ----------------
__global__ __launch_bounds__(256) void k_norm(float* __restrict__ out) {
    int row = blockIdx.y;
    int n = blockIdx.x*256 + threadIdx.x;
    if (n < Ntok) {
        size_t i = (size_t)row*Ntok + n;
        out[i] = __expf(out[i]) * g_Tinv[row];
    }
}

// ---------------- launch ----------------
extern "C" void kernel_launch(void* const* d_in, const int* in_sizes, int n_in,
                              void* d_out, int out_size) {
    const float* x       = (const float*)d_in[0];
    const float* ln1_g   = (const float*)d_in[1];
    const float* ln1_b   = (const float*)d_in[2];
    const float* kv0_w   = (const float*)d_in[3];
    const float* q0_w    = (const float*)d_in[4];
    const float* proj0_w = (const float*)d_in[5];
    const float* proj0_b = (const float*)d_in[6];
    const float* ln2_g   = (const float*)d_in[7];
    const float* ln2_b   = (const float*)d_in[8];
    const float* fc1_w   = (const float*)d_in[9];
    const float* fc1_b   = (const float*)d_in[10];
    const float* fc2_w   = (const float*)d_in[11];
    const float* fc2_b   = (const float*)d_in[12];
    const float* ln3_g   = (const float*)d_in[13];
    const float* ln3_b   = (const float*)d_in[14];
    const float* kv1_w   = (const float*)d_in[15];
    const float* q1_w    = (const float*)d_in[16];
    float* out = (float*)d_out;

    cudaFuncSetAttribute(k_gemm_mma, cudaFuncAttributeMaxDynamicSharedMemorySize, GEMM_SMEM);
    cudaFuncSetAttribute(k_attn0_mma, cudaFuncAttributeMaxDynamicSharedMemorySize, ATT_SMEM);

    k_prep<<<1536, 256>>>(kv0_w, kv1_w, ln1_g, ln1_b, ln3_g, ln3_b);
    k_stats<<<(M_ROWS + 7)/8, dim3(32, 8)>>>(x);
    k_gemm_mma<<<dim3(12, 578), 256, GEMM_SMEM>>>(x);
    k_q0<<<Bq*Tt, 512>>>(x, q0_w, ln1_g, ln1_b);
    k_attn0_mma<<<dim3(Bq*Hh, NSEG), 256, ATT_SMEM>>>();
    k_ce<<<Bq*Tt, 512>>>();
    k_cls<<<(Bq*Tt)/2, 512>>>(x, proj0_w, proj0_b, ln2_g, ln2_b,
                              fc1_w, fc1_b, fc2_w, fc2_b, ln3_g, ln3_b, kv1_w, q1_w);
    k_logits_mma<<<dim3(Bq*Hh, NSEG), 256>>>(out);
    k_reduce<<<Bq*Hh, 32>>>();
    k_norm<<<dim3((Ntok + 255)/256, Bq*Hh*Tt), 256>>>(out);
}

// round 6
// speedup vs baseline: 2.1575x; 1.0037x over previous
#include <cuda_runtime.h>
#include <cstdint>
#include <math.h>

#define Bq 8
#define Ntok 9237
#define Cc 512
#define Tt 21
#define Hh 8
#define Dd 64
#define HIDN 2048
#define M_ROWS (Bq*Ntok)          // 73896
#define EPSV 1e-5f
#define SCALEV 0.125f
#define NSEG 37                    // ceil(9237/256)
#define PSTR 72                    // smem row stride (floats): conflict-free frags
#define MTILES 578                 // ceil(73896/128)

// ---------------- static scratch (no allocations allowed) ----------------
__device__ __align__(16) float g_mean[M_ROWS];
__device__ __align__(16) float g_rstd[M_ROWS];
__device__ __align__(16) uint32_t g_Afrag[(size_t)MTILES*16*4096];  // LN'd A, tf32, fragment order
__device__ __align__(16) float g_Bfrag[1536*512];   // fragment-packed, gamma-folded, tf32
__device__ __align__(16) float g_biasc[1536];
__device__ __align__(16) float g_K0[(size_t)Bq*Hh*Ntok*Dd];
__device__ __align__(16) float g_V0[(size_t)Bq*Hh*Ntok*Dd];
__device__ __align__(16) float g_K1[(size_t)Bq*Hh*Ntok*Dd];
__device__ __align__(16) float g_q0[Bq*Tt*Cc];
__device__ __align__(16) float g_q1[Bq*Tt*Cc];
__device__ __align__(16) float g_Pacc[(size_t)Bq*Hh*NSEG*Tt*Dd];
__device__ __align__(16) float g_Psum[Bq*Hh*NSEG*Tt];
__device__ __align__(16) float g_ce[Bq*Tt*Cc];
__device__ __align__(16) float g_Fsum[Bq*Hh*NSEG*Tt];
__device__ __align__(16) float g_Tinv[Bq*Hh*Tt];

// ---------------- helpers ----------------
__device__ __forceinline__ uint32_t smem_u32(const void* p) {
    uint32_t a;
    asm("{ .reg .u64 t; cvta.to.shared.u64 t, %1; cvt.u32.u64 %0, t; }" : "=r"(a) : "l"(p));
    return a;
}
__device__ __forceinline__ uint32_t tf32r(float f) {
    uint32_t u; asm("cvt.rna.tf32.f32 %0, %1;" : "=r"(u) : "f"(f)); return u;
}
__device__ __forceinline__ void cp_async16(uint32_t smem, const void* g) {
    asm volatile("cp.async.cg.shared.global [%0], [%1], 16;" :: "r"(smem), "l"(g));
}
__device__ __forceinline__ void cp_async16z(uint32_t smem, const void* g, int szbytes) {
    asm volatile("cp.async.cg.shared.global [%0], [%1], 16, %2;"
                 :: "r"(smem), "l"(g), "r"(szbytes));
}
#define CP_COMMIT() asm volatile("cp.async.commit_group;" ::: "memory")
#define CP_WAIT0()  asm volatile("cp.async.wait_group 0;" ::: "memory")
#define CP_WAIT1()  asm volatile("cp.async.wait_group 1;" ::: "memory")

__device__ __forceinline__ void mma1688(float* c, const uint32_t* a, const uint32_t* b) {
    asm volatile(
        "mma.sync.aligned.m16n8k8.row.col.f32.tf32.tf32.f32 "
        "{%0,%1,%2,%3}, {%4,%5,%6,%7}, {%8,%9}, {%0,%1,%2,%3};"
        : "+f"(c[0]), "+f"(c[1]), "+f"(c[2]), "+f"(c[3])
        : "r"(a[0]), "r"(a[1]), "r"(a[2]), "r"(a[3]), "r"(b[0]), "r"(b[1]));
}

// ---------------- K1: prep fragment-packed fused weights + folded bias ----------------
__global__ __launch_bounds__(256) void k_prep(const float* __restrict__ kv0_w,
                                              const float* __restrict__ kv1_w,
                                              const float* __restrict__ g1, const float* __restrict__ b1,
                                              const float* __restrict__ g3, const float* __restrict__ b3) {
    int n = blockIdx.x;          // 0..1535
    const float *W, *g, *b; int col;
    if (n < 1024) { W = kv0_w; g = g1; b = b1; col = n; }
    else          { W = kv1_w; g = g3; b = b3; col = n - 1024; }
    int bx = n >> 7;
    int np = n & 127;
    int n8 = np >> 3, gg = np & 7;
    float partial = 0.f;
    for (int k = threadIdx.x; k < 512; k += 256) {
        float w = W[(size_t)k*1024 + col] * g[k];
        int c  = k >> 5;
        int kc = k & 31;
        int ks = kc >> 3, kin = kc & 7;
        int t = kin & 3, reg = kin >> 2;
        int lane = gg*4 + t;
        size_t idx = (size_t)(bx*16 + c)*4096 + ((n8*4 + ks)*32 + lane)*2 + reg;
        g_Bfrag[idx] = __uint_as_float(tf32r(w));
        partial += b[k] * w;
    }
    __shared__ float red[256];
    red[threadIdx.x] = partial; __syncthreads();
    for (int s = 128; s; s >>= 1) {
        if (threadIdx.x < s) red[threadIdx.x] += red[threadIdx.x + s];
        __syncthreads();
    }
    if (threadIdx.x == 0) g_biasc[n] = red[0];
}

// ---------------- K2: per-row LN stats ----------------
__global__ void k_stats(const float* __restrict__ x) {
    int row = blockIdx.x * 8 + threadIdx.y;
    if (row >= M_ROWS) return;
    const float4* xr = (const float4*)(x + (size_t)row*512);
    float s = 0.f, sq = 0.f;
    for (int i = threadIdx.x; i < 128; i += 32) {
        float4 v = xr[i];
        s  += v.x + v.y + v.z + v.w;
        sq += v.x*v.x + v.y*v.y + v.z*v.z + v.w*v.w;
    }
    for (int o = 16; o; o >>= 1) {
        s  += __shfl_down_sync(0xffffffffu, s, o);
        sq += __shfl_down_sync(0xffffffffu, sq, o);
    }
    if (threadIdx.x == 0) {
        float m = s * (1.f/512.f);
        float var = sq * (1.f/512.f) - m*m;
        g_mean[row] = m;
        g_rstd[row] = rsqrtf(var + EPSV);
    }
}

// ---------------- K2b: pack LN(x) into A-fragment order (tf32) ----------------
// per m-tile (128 rows) x chunk (32 k): 4096 u32
// idx = ((mtile*4 + ks)*32 + lane)*4 + reg
//   row = mtile*16 + (reg&1)*8 + (lane>>2); k = chunk*32 + ks*8 + (lane&3) + (reg>>1)*4
__global__ __launch_bounds__(256) void k_packA(const float* __restrict__ x) {
    __shared__ float ms[128], rs[128];
    int by = blockIdx.x;
    int rowBase = by*128;
    int tid = threadIdx.x;
    if (tid < 128) {
        int r = rowBase + tid;
        bool ok = r < M_ROWS;
        ms[tid] = ok ? g_mean[r] : 0.f;
        rs[tid] = ok ? g_rstd[r] : 0.f;
    }
    __syncthreads();
    uint32_t* dst = g_Afrag + (size_t)by*16*4096;
    for (int c = 0; c < 16; c++) {
        #pragma unroll
        for (int it = 0; it < 16; it++) {          // FIX: full 4096 coverage
            int f = tid + it*256;
            int reg = f & 3, lane = (f >> 2) & 31, ks = (f >> 7) & 3, mtile = f >> 9;
            int g = lane >> 2, t4 = lane & 3;
            int rl = mtile*16 + (reg & 1)*8 + g;
            int k = c*32 + ks*8 + t4 + (reg >> 1)*4;
            int r = rowBase + rl;
            float v = 0.f;
            if (r < M_ROWS) v = (x[(size_t)r*512 + k] - ms[rl]) * rs[rl];
            dst[c*4096 + f] = tf32r(v);
        }
    }
}

// ---------------- K3: pure-stream tf32 mma GEMM (3-stage cp.async) ----------------
#define GEMM_SMEM (3*32768)

__global__ __launch_bounds__(256, 2) void k_gemm_mma() {
    extern __shared__ uint32_t dsmu[];     // 3 stages x (A 4096 + B 4096) u32

    const int tid = threadIdx.x;
    const int bx = blockIdx.x;             // 0..11 (N tiles)
    const int by = blockIdx.y;             // 0..577 (M tiles)
    const int colBase = bx * 128;
    const int rowBase = by * 128;

    const int lane = tid & 31, wid = tid >> 5;
    const int warp_m = wid & 1, warp_n = wid >> 1;
    const int g = lane >> 2, t4 = lane & 3;

    const uint32_t sbase = smem_u32(dsmu);
    const uint32_t* Asrc = g_Afrag + (size_t)by*16*4096;
    const uint32_t* Bsrc = (const uint32_t*)g_Bfrag + (size_t)bx*16*4096;

    auto issue = [&](int c, int s) {
        uint32_t dstA = sbase + (uint32_t)s*32768;
        const uint32_t* a = Asrc + c*4096;
        const uint32_t* b = Bsrc + c*4096;
        #pragma unroll
        for (int it = 0; it < 4; it++) {
            int off = (tid + it*256)*4;
            cp_async16(dstA + off*4, a + off);
            cp_async16(dstA + 16384 + off*4, b + off);
        }
        CP_COMMIT();
    };

    float acc[4][4][4];
    #pragma unroll
    for (int i = 0; i < 4; i++)
        #pragma unroll
        for (int j = 0; j < 4; j++)
            #pragma unroll
            for (int k = 0; k < 4; k++) acc[i][j][k] = 0.f;

    issue(0, 0); issue(1, 1);

    int s = 0;
    for (int c = 0; c < 16; c++) {
        CP_WAIT1();
        __syncthreads();
        if (c + 2 < 16) issue(c + 2, (s + 2 == 3) ? (s - 1) : (s + 2) > 2 ? s - 1 : s + 2);
        else CP_COMMIT();

        const uint32_t* Af = dsmu + s*8192;
        const uint32_t* Bf = dsmu + s*8192 + 4096;
        #pragma unroll
        for (int ks = 0; ks < 4; ks++) {
            uint32_t bfr[4][2];
            #pragma unroll
            for (int nf = 0; nf < 4; nf++) {
                int fi = (((warp_n*4 + nf)*4 + ks)*32 + lane)*2;
                bfr[nf][0] = Bf[fi];
                bfr[nf][1] = Bf[fi + 1];
            }
            #pragma unroll
            for (int mf = 0; mf < 4; mf++) {
                int ai = (((warp_m*4 + mf)*4 + ks)*32 + lane)*4;
                uint4 av = *(const uint4*)(Af + ai);
                uint32_t afr[4] = {av.x, av.y, av.z, av.w};
                #pragma unroll
                for (int nf = 0; nf < 4; nf++)
                    mma1688(acc[mf][nf], afr, bfr[nf]);
            }
        }
        s = (s == 2) ? 0 : s + 1;
    }

    // epilogue: scatter to K0/V0/K1 with folded bias
    const int region = bx >> 2;
    float* dstB = (region == 0) ? g_K0 : (region == 1) ? g_V0 : g_K1;
    float2 bias[4];
    #pragma unroll
    for (int nf = 0; nf < 4; nf++) {
        int j = colBase + warp_n*32 + nf*8 + t4*2;
        bias[nf] = *(const float2*)(g_biasc + j);
    }
    #pragma unroll
    for (int mf = 0; mf < 4; mf++) {
        #pragma unroll
        for (int hi = 0; hi < 2; hi++) {
            int r = rowBase + warp_m*64 + mf*16 + g + hi*8;
            if (r >= M_ROWS) continue;
            int bb = r / Ntok, nt = r % Ntok;
            #pragma unroll
            for (int nf = 0; nf < 4; nf++) {
                int j = colBase + warp_n*32 + nf*8 + t4*2;
                int h = (j >> 6) & 7, d = j & 63;
                float2 v;
                v.x = acc[mf][nf][hi*2 + 0] + bias[nf].x;
                v.y = acc[mf][nf][hi*2 + 1] + bias[nf].y;
                *(float2*)(dstB + (((size_t)bb*Hh + h)*Ntok + nt)*64 + d) = v;
            }
        }
    }
}

// ---------------- K4: q0mat = ln1(x[:, :T]) @ q0_w ----------------
__global__ __launch_bounds__(512) void k_q0(const float* __restrict__ x,
                                            const float* __restrict__ q0_w,
                                            const float* __restrict__ g1,
                                            const float* __restrict__ b1) {
    int r = blockIdx.x;
    int b = r / Tt, t = r % Tt;
    int row = b*Ntok + t;
    __shared__ float y[512];
    int tid = threadIdx.x;
    float m = g_mean[row], rs = g_rstd[row];
    y[tid] = (x[(size_t)row*512 + tid] - m)*rs*g1[tid] + b1[tid];
    __syncthreads();
    float acc = 0.f;
    for (int k = 0; k < 512; k++) acc = fmaf(y[k], q0_w[(size_t)k*512 + tid], acc);
    g_q0[(size_t)r*512 + tid] = acc;
}

// ---------------- K5: attn0 via mma (QK -> exp -> PV), unnormalized partials ----
#define ATT_SMEM ((32*PSTR + 64*PSTR + 64*PSTR + 32*PSTR)*4 + 8*32*4)

__global__ __launch_bounds__(256) void k_attn0_mma() {
    extern __shared__ float sm[];
    float* Qs = sm;                      // [32][PSTR]
    float* Ks = Qs + 32*PSTR;            // [64][PSTR]
    float* Vs = Ks + 64*PSTR;            // [64][PSTR]
    float* Ps = Vs + 64*PSTR;            // [32][PSTR]
    float* ws = Ps + 32*PSTR;            // [8][32]

    int bh = blockIdx.x, seg = blockIdx.y;
    int b = bh >> 3, h = bh & 7;
    int tid = threadIdx.x;
    int lane = tid & 31, w = tid >> 5;
    int g = lane >> 2, t4 = lane & 3;

    for (int i = tid; i < 32*64; i += 256) {
        int t = i >> 6, d = i & 63;
        float v = (t < Tt) ? SCALEV * g_q0[(size_t)b*Tt*512 + h*(Tt*Dd) + t*Dd + d] : 0.f;
        Qs[t*PSTR + d] = __uint_as_float(tf32r(v));
    }
    __syncthreads();

    const float* Kb = g_K0 + (size_t)bh*Ntok*64;
    const float* Vb = g_V0 + (size_t)bh*Ntok*64;
    uint32_t KsU = smem_u32(Ks), VsU = smem_u32(Vs);

    float o[2][4];
    #pragma unroll
    for (int m = 0; m < 2; m++)
        #pragma unroll
        for (int e = 0; e < 4; e++) o[m][e] = 0.f;
    float ssum[4] = {0.f, 0.f, 0.f, 0.f};

    for (int ch = 0; ch < 4; ch++) {
        int nc = seg*256 + ch*64;
        #pragma unroll
        for (int it = 0; it < 4; it++) {
            int slot = tid + it*256;
            int r = slot >> 4, c4 = (slot & 15)*4;
            int gn = nc + r;
            bool p = gn < Ntok;
            int gc = p ? gn : 0;
            int sz = p ? 16 : 0;
            cp_async16z(KsU + (r*PSTR + c4)*4, Kb + (size_t)gc*64 + c4, sz);
            cp_async16z(VsU + (r*PSTR + c4)*4, Vb + (size_t)gc*64 + c4, sz);
        }
        CP_COMMIT(); CP_WAIT0();
        __syncthreads();

        float s[2][4];
        #pragma unroll
        for (int m = 0; m < 2; m++)
            #pragma unroll
            for (int e = 0; e < 4; e++) s[m][e] = 0.f;
        #pragma unroll
        for (int ks = 0; ks < 8; ks++) {
            uint32_t bfr[2];
            bfr[0] = __float_as_uint(Ks[(w*8 + g)*PSTR + ks*8 + t4]);
            bfr[1] = __float_as_uint(Ks[(w*8 + g)*PSTR + ks*8 + t4 + 4]);
            #pragma unroll
            for (int m = 0; m < 2; m++) {
                uint32_t afr[4];
                int ab = (m*16 + g)*PSTR + ks*8 + t4;
                afr[0] = __float_as_uint(Qs[ab]);
                afr[1] = __float_as_uint(Qs[ab + 8*PSTR]);
                afr[2] = __float_as_uint(Qs[ab + 4]);
                afr[3] = __float_as_uint(Qs[ab + 8*PSTR + 4]);
                mma1688(s[m], afr, bfr);
            }
        }

        int tok0 = nc + w*8 + 2*t4;
        int tok1 = tok0 + 1;
        #pragma unroll
        for (int m = 0; m < 2; m++) {
            float e0 = __expf(s[m][0]), e1 = __expf(s[m][1]);
            float e2 = __expf(s[m][2]), e3 = __expf(s[m][3]);
            if (tok0 >= Ntok) { e0 = 0.f; e2 = 0.f; }
            if (tok1 >= Ntok) { e1 = 0.f; e3 = 0.f; }
            e0 = __uint_as_float(tf32r(e0)); e1 = __uint_as_float(tf32r(e1));
            e2 = __uint_as_float(tf32r(e2)); e3 = __uint_as_float(tf32r(e3));
            float2 p01 = make_float2(e0, e1), p23 = make_float2(e2, e3);
            *(float2*)&Ps[(m*16 + g)*PSTR + w*8 + 2*t4] = p01;
            *(float2*)&Ps[(m*16 + g + 8)*PSTR + w*8 + 2*t4] = p23;
            float r0 = e0 + e1, r1 = e2 + e3;
            r0 += __shfl_xor_sync(0xffffffffu, r0, 1);
            r0 += __shfl_xor_sync(0xffffffffu, r0, 2);
            r1 += __shfl_xor_sync(0xffffffffu, r1, 1);
            r1 += __shfl_xor_sync(0xffffffffu, r1, 2);
            if (t4 == 0) { ssum[m*2] += r0; ssum[m*2 + 1] += r1; }
        }
        __syncthreads();

        #pragma unroll
        for (int ks = 0; ks < 8; ks++) {
            uint32_t bfr[2];
            bfr[0] = __float_as_uint(Vs[(ks*8 + t4)*PSTR + w*8 + g]);
            bfr[1] = __float_as_uint(Vs[(ks*8 + t4 + 4)*PSTR + w*8 + g]);
            #pragma unroll
            for (int m = 0; m < 2; m++) {
                uint32_t afr[4];
                int ab = (m*16 + g)*PSTR + ks*8 + t4;
                afr[0] = __float_as_uint(Ps[ab]);
                afr[1] = __float_as_uint(Ps[ab + 8*PSTR]);
                afr[2] = __float_as_uint(Ps[ab + 4]);
                afr[3] = __float_as_uint(Ps[ab + 8*PSTR + 4]);
                mma1688(o[m], afr, bfr);
            }
        }
        __syncthreads();
    }

    if (t4 == 0) {
        ws[w*32 + g]      = ssum[0];
        ws[w*32 + g + 8]  = ssum[1];
        ws[w*32 + 16 + g] = ssum[2];
        ws[w*32 + 24 + g] = ssum[3];
    }
    __syncthreads();
    if (tid < Tt) {
        float s = 0.f;
        #pragma unroll
        for (int wq = 0; wq < 8; wq++) s += ws[wq*32 + tid];
        g_Psum[((size_t)bh*NSEG + seg)*Tt + tid] = s;
    }

    #pragma unroll
    for (int m = 0; m < 2; m++) {
        int r0 = m*16 + g, r1 = m*16 + g + 8;
        int d0 = w*8 + 2*t4;
        if (r0 < Tt)
            *(float2*)&g_Pacc[(((size_t)bh*NSEG + seg)*Tt + r0)*64 + d0] =
                make_float2(o[m][0], o[m][1]);
        if (r1 < Tt)
            *(float2*)&g_Pacc[(((size_t)bh*NSEG + seg)*Tt + r1)*64 + d0] =
                make_float2(o[m][2], o[m][3]);
    }
}

// ---------------- K6: combine partials -> ce [B,T,512] ----------------
__global__ __launch_bounds__(512) void k_ce() {
    int r = blockIdx.x;
    int b = r / Tt, t = r % Tt;
    int c = threadIdx.x;
    int h = c >> 6, d = c & 63;
    int bh = b*8 + h;
    float accv = 0.f, s = 0.f;
    for (int sg = 0; sg < NSEG; sg++) {
        accv += g_Pacc[(((size_t)bh*NSEG + sg)*Tt + t)*64 + d];
        s    += g_Psum[((size_t)bh*NSEG + sg)*Tt + t];
    }
    g_ce[(size_t)r*512 + c] = accv / s;
}

// ---------------- helper: block layernorm over 512 ----------------
__device__ void ln_row512(const float* in, float* out, const float* g, const float* bb,
                          float* red, int tid) {
    float v = in[tid];
    float s = v, sq = v*v;
    for (int o = 16; o; o >>= 1) {
        s  += __shfl_down_sync(0xffffffffu, s, o);
        sq += __shfl_down_sync(0xffffffffu, sq, o);
    }
    int wid = tid >> 5, lane = tid & 31;
    if (lane == 0) { red[wid] = s; red[16 + wid] = sq; }
    __syncthreads();
    if (tid == 0) {
        float S = 0.f, SQ = 0.f;
        for (int w = 0; w < 16; w++) { S += red[w]; SQ += red[16 + w]; }
        float m = S * (1.f/512.f);
        red[32] = m;
        red[33] = rsqrtf(SQ * (1.f/512.f) - m*m + EPSV);
    }
    __syncthreads();
    float m = red[32], rs = red[33];
    out[tid] = (v - m)*rs*g[tid] + bb[tid];
    __syncthreads();
}

// ---------------- K7: cls path (proj + MLP + LN3 + k1/q1 overwrite) ----------------
__global__ __launch_bounds__(512) void k_cls(const float* __restrict__ x,
        const float* __restrict__ proj0_w, const float* __restrict__ proj0_b,
        const float* __restrict__ g2, const float* __restrict__ b2,
        const float* __restrict__ fc1_w, const float* __restrict__ fc1_b,
        const float* __restrict__ fc2_w, const float* __restrict__ fc2_b,
        const float* __restrict__ g3, const float* __restrict__ b3,
        const float* __restrict__ kv1_w, const float* __restrict__ q1_w) {
    __shared__ float cer[2][512];
    __shared__ float cls[2][512];
    __shared__ float yb[2][512];
    __shared__ float hb[2][2048];
    __shared__ float red[40];
    int tid = threadIdx.x;
    int rows[2] = {blockIdx.x*2, blockIdx.x*2 + 1};

    for (int i = 0; i < 2; i++) cer[i][tid] = g_ce[(size_t)rows[i]*512 + tid];
    __syncthreads();
    for (int i = 0; i < 2; i++) {
        int b = rows[i] / Tt, t = rows[i] % Tt;
        float acc = proj0_b[tid];
        for (int k = 0; k < 512; k++) acc = fmaf(cer[i][k], proj0_w[(size_t)k*512 + tid], acc);
        cls[i][tid] = x[((size_t)b*Ntok + t)*512 + tid] + acc;
    }
    __syncthreads();
    for (int i = 0; i < 2; i++) ln_row512(cls[i], yb[i], g2, b2, red, tid);
    for (int i = 0; i < 2; i++)
        for (int jj = 0; jj < 4; jj++) {
            int j = tid + jj*512;
            float a = fc1_b[j];
            for (int k = 0; k < 512; k++) a = fmaf(yb[i][k], fc1_w[(size_t)k*2048 + j], a);
            hb[i][j] = 0.5f*a*(1.0f + erff(a*0.70710678118654752f));
        }
    __syncthreads();
    for (int i = 0; i < 2; i++) {
        float a = fc2_b[tid];
        for (int k = 0; k < 2048; k++) a = fmaf(hb[i][k], fc2_w[(size_t)k*512 + tid], a);
        cls[i][tid] += a;
    }
    __syncthreads();
    for (int i = 0; i < 2; i++) ln_row512(cls[i], yb[i], g3, b3, red, tid);
    for (int i = 0; i < 2; i++) {
        int b = rows[i] / Tt, t = rows[i] % Tt;
        float ak = 0.f, aq = 0.f;
        for (int k = 0; k < 512; k++) {
            float y = yb[i][k];
            ak = fmaf(y, kv1_w[(size_t)k*1024 + tid], ak);
            aq = fmaf(y, q1_w[(size_t)k*512 + tid], aq);
        }
        int h = tid >> 6, d = tid & 63;
        g_K1[(((size_t)b*Hh + h)*Ntok + t)*64 + d] = ak;
        g_q1[(size_t)rows[i]*512 + tid] = aq;
    }
}

// ---------------- K8a: final logits via mma + per-segment sumexp ----------------
__global__ __launch_bounds__(256) void k_logits_mma(float* __restrict__ out) {
    __shared__ float Qs[32*PSTR];
    __shared__ float Ks[64*PSTR];
    __shared__ float ws[8*32];

    int bh = blockIdx.x, seg = blockIdx.y;
    int b = bh >> 3, h = bh & 7;
    int tid = threadIdx.x;
    int lane = tid & 31, w = tid >> 5;
    int g = lane >> 2, t4 = lane & 3;

    for (int i = tid; i < 32*64; i += 256) {
        int t = i >> 6, d = i & 63;
        float v = (t < Tt) ? SCALEV * g_q1[(size_t)b*Tt*512 + h*(Tt*Dd) + t*Dd + d] : 0.f;
        Qs[t*PSTR + d] = __uint_as_float(tf32r(v));
    }
    __syncthreads();

    const float* Kb = g_K1 + (size_t)bh*Ntok*64;
    uint32_t KsU = smem_u32(Ks);
    float ssum[4] = {0.f, 0.f, 0.f, 0.f};

    for (int ch = 0; ch < 4; ch++) {
        int nc = seg*256 + ch*64;
        #pragma unroll
        for (int it = 0; it < 4; it++) {
            int slot = tid + it*256;
            int r = slot >> 4, c4 = (slot & 15)*4;
            int gn = nc + r;
            bool p = gn < Ntok;
            int gc = p ? gn : 0;
            int sz = p ? 16 : 0;
            cp_async16z(KsU + (r*PSTR + c4)*4, Kb + (size_t)gc*64 + c4, sz);
        }
        CP_COMMIT(); CP_WAIT0();
        __syncthreads();

        float s[2][4];
        #pragma unroll
        for (int m = 0; m < 2; m++)
            #pragma unroll
            for (int e = 0; e < 4; e++) s[m][e] = 0.f;
        #pragma unroll
        for (int ks = 0; ks < 8; ks++) {
            uint32_t bfr[2];
            bfr[0] = __float_as_uint(Ks[(w*8 + g)*PSTR + ks*8 + t4]);
            bfr[1] = __float_as_uint(Ks[(w*8 + g)*PSTR + ks*8 + t4 + 4]);
            #pragma unroll
            for (int m = 0; m < 2; m++) {
                uint32_t afr[4];
                int ab = (m*16 + g)*PSTR + ks*8 + t4;
                afr[0] = __float_as_uint(Qs[ab]);
                afr[1] = __float_as_uint(Qs[ab + 8*PSTR]);
                afr[2] = __float_as_uint(Qs[ab + 4]);
                afr[3] = __float_as_uint(Qs[ab + 8*PSTR + 4]);
                mma1688(s[m], afr, bfr);
            }
        }

        int tok0 = nc + w*8 + 2*t4;
        int tok1 = tok0 + 1;
        #pragma unroll
        for (int m = 0; m < 2; m++) {
            int r0 = m*16 + g, r1 = m*16 + g + 8;
            if (r0 < Tt) {
                size_t ob = ((size_t)bh*Tt + r0)*Ntok;
                if (tok0 < Ntok) out[ob + tok0] = s[m][0];
                if (tok1 < Ntok) out[ob + tok1] = s[m][1];
            }
            if (r1 < Tt) {
                size_t ob = ((size_t)bh*Tt + r1)*Ntok;
                if (tok0 < Ntok) out[ob + tok0] = s[m][2];
                if (tok1 < Ntok) out[ob + tok1] = s[m][3];
            }
            float e0 = __expf(s[m][0]), e1 = __expf(s[m][1]);
            float e2 = __expf(s[m][2]), e3 = __expf(s[m][3]);
            if (tok0 >= Ntok) { e0 = 0.f; e2 = 0.f; }
            if (tok1 >= Ntok) { e1 = 0.f; e3 = 0.f; }
            float r0s = e0 + e1, r1s = e2 + e3;
            r0s += __shfl_xor_sync(0xffffffffu, r0s, 1);
            r0s += __shfl_xor_sync(0xffffffffu, r0s, 2);
            r1s += __shfl_xor_sync(0xffffffffu, r1s, 1);
            r1s += __shfl_xor_sync(0xffffffffu, r1s, 2);
            if (t4 == 0) { ssum[m*2] += r0s; ssum[m*2 + 1] += r1s; }
        }
        __syncthreads();
    }

    if (t4 == 0) {
        ws[w*32 + g]      = ssum[0];
        ws[w*32 + g + 8]  = ssum[1];
        ws[w*32 + 16 + g] = ssum[2];
        ws[w*32 + 24 + g] = ssum[3];
    }
    __syncthreads();
    if (tid < Tt) {
        float s = 0.f;
        #pragma unroll
        for (int wq = 0; wq < 8; wq++) s += ws[wq*32 + tid];
        g_Fsum[((size_t)bh*NSEG + seg)*Tt + tid] = s;
    }
}

// ---------------- K8b: reduce sums per (bh,t) ----------------
__global__ void k_reduce() {
    int bh = blockIdx.x;
    int t = threadIdx.x;
    if (t >= Tt) return;
    float S = 0.f;
    for (int s = 0; s < NSEG; s++)
        S += g_Fsum[((size_t)bh*NSEG + s)*Tt + t];
    g_Tinv[bh*Tt + t] = 1.f / S;
}

// ---------------- K8c: normalize logits in place ----------------
__global__ __launch_bounds__(256) void k_norm(float* __restrict__ out) {
    int row = blockIdx.y;
    int n = blockIdx.x*256 + threadIdx.x;
    if (n < Ntok) {
        size_t i = (size_t)row*Ntok + n;
        out[i] = __expf(out[i]) * g_Tinv[row];
    }
}

// ---------------- launch ----------------
extern "C" void kernel_launch(void* const* d_in, const int* in_sizes, int n_in,
                              void* d_out, int out_size) {
    const float* x       = (const float*)d_in[0];
    const float* ln1_g   = (const float*)d_in[1];
    const float* ln1_b   = (const float*)d_in[2];
    const float* kv0_w   = (const float*)d_in[3];
    const float* q0_w    = (const float*)d_in[4];
    const float* proj0_w = (const float*)d_in[5];
    const float* proj0_b = (const float*)d_in[6];
    const float* ln2_g   = (const float*)d_in[7];
    const float* ln2_b   = (const float*)d_in[8];
    const float* fc1_w   = (const float*)d_in[9];
    const float* fc1_b   = (const float*)d_in[10];
    const float* fc2_w   = (const float*)d_in[11];
    const float* fc2_b   = (const float*)d_in[12];
    const float* ln3_g   = (const float*)d_in[13];
    const float* ln3_b   = (const float*)d_in[14];
    const float* kv1_w   = (const float*)d_in[15];
    const float* q1_w    = (const float*)d_in[16];
    float* out = (float*)d_out;

    cudaFuncSetAttribute(k_gemm_mma, cudaFuncAttributeMaxDynamicSharedMemorySize, GEMM_SMEM);
    cudaFuncSetAttribute(k_attn0_mma, cudaFuncAttributeMaxDynamicSharedMemorySize, ATT_SMEM);

    k_prep<<<1536, 256>>>(kv0_w, kv1_w, ln1_g, ln1_b, ln3_g, ln3_b);
    k_stats<<<(M_ROWS + 7)/8, dim3(32, 8)>>>(x);
    k_packA<<<MTILES, 256>>>(x);
    k_gemm_mma<<<dim3(12, MTILES), 256, GEMM_SMEM>>>();
    k_q0<<<Bq*Tt, 512>>>(x, q0_w, ln1_g, ln1_b);
    k_attn0_mma<<<dim3(Bq*Hh, NSEG), 256, ATT_SMEM>>>();
    k_ce<<<Bq*Tt, 512>>>();
    k_cls<<<(Bq*Tt)/2, 512>>>(x, proj0_w, proj0_b, ln2_g, ln2_b,
                              fc1_w, fc1_b, fc2_w, fc2_b, ln3_g, ln3_b, kv1_w, q1_w);
    k_logits_mma<<<dim3(Bq*Hh, NSEG), 256>>>(out);
    k_reduce<<<Bq*Hh, 32>>>();
    k_norm<<<dim3((Ntok + 255)/256, Bq*Hh*Tt), 256>>>(out);
}